// round 3
// baseline (speedup 1.0000x reference)
#include <cuda_runtime.h>
#include <math.h>

#define NN 50000
#define NE 800000
#define NG 64

// ---------------- scratch (device globals; no allocation allowed) -------------
__device__ float g_bufA[NN * 256];
__device__ float g_bufB[NN * 256];
__device__ float g_bufC[NN * 256];
__device__ float g_dinv[NN];
__device__ int   g_cnt[NN];
__device__ int   g_off[NN + 1];
__device__ int   g_cur[NN];
__device__ int   g_csr_src[NE];
__device__ float g_csr_norm[NE];
__device__ float g_pool[NG * 256];

// device-side buffer selector (no host symbol-address queries)
__device__ __forceinline__ float* bufsel(int s) {
    return (s == 0) ? g_bufA : (s == 1) ? g_bufB : g_bufC;
}

// ---------------- preprocessing ----------------------------------------------

__global__ void zero_cnt_kernel() {
    int i = blockIdx.x * blockDim.x + threadIdx.x;
    if (i < NN) g_cnt[i] = 0;
}

__global__ void count_kernel(const int* __restrict__ dst) {
    int e = blockIdx.x * blockDim.x + threadIdx.x;
    if (e < NE) atomicAdd(&g_cnt[dst[e]], 1);
}

// single-block chunked Hillis-Steele exclusive scan over g_cnt -> g_off
__global__ void scan_kernel() {
    __shared__ int s[1024];
    int tid = threadIdx.x;
    int carry = 0;
    const int CH = (NN + 1023) / 1024;
    for (int c = 0; c < CH; c++) {
        int idx = c * 1024 + tid;
        int v = (idx < NN) ? g_cnt[idx] : 0;
        s[tid] = v;
        __syncthreads();
        for (int o = 1; o < 1024; o <<= 1) {
            int t = (tid >= o) ? s[tid - o] : 0;
            __syncthreads();
            s[tid] += t;
            __syncthreads();
        }
        if (idx < NN) g_off[idx] = s[tid] - v + carry;
        carry += s[1023];
        __syncthreads();
    }
    if (tid == 0) g_off[NN] = carry;
}

__global__ void dinv_cur_kernel() {
    int v = blockIdx.x * blockDim.x + threadIdx.x;
    if (v < NN) {
        g_dinv[v] = rsqrtf((float)g_cnt[v] + 1.0f);  // +1 self loop
        g_cur[v] = g_off[v];
    }
}

__global__ void fill_kernel(const int* __restrict__ src,
                            const int* __restrict__ dst) {
    int e = blockIdx.x * blockDim.x + threadIdx.x;
    if (e < NE) {
        int s = src[e];
        int d = dst[e];
        int pos = atomicAdd(&g_cur[d], 1);
        g_csr_src[pos] = s;
        g_csr_norm[pos] = g_dinv[s] * g_dinv[d];
    }
}

// ---------------- GEMMs --------------------------------------------------------

// layer 1: [N,9] @ [9,128] -> g_bufB; tiny K, memory bound
__global__ __launch_bounds__(256) void gemm_k9(const float* __restrict__ x,
                                               const float* __restrict__ W) {
    __shared__ float Ws[9 * 128];
    int tid = threadIdx.x;
    for (int i = tid; i < 9 * 128; i += 256) Ws[i] = W[i];
    __syncthreads();
    int v = blockIdx.x * 2 + (tid >> 7);
    int f = tid & 127;
    if (v < NN) {
        float acc = 0.f;
#pragma unroll
        for (int k = 0; k < 9; k++) acc += x[v * 9 + k] * Ws[k * 128 + f];
        g_bufB[v * 128 + f] = acc;
    }
}

// [M,K] @ [K,256] fp32, BM=64, BN=256, BK=16, 8x8 register tile / thread
__global__ __launch_bounds__(256) void gemm_f256(int selA, int selY,
                                                 const float* __restrict__ W,
                                                 int M, int K) {
    const float* A = bufsel(selA);
    float* Y = bufsel(selY);
    __shared__ float As[16][66];   // padded -> STS-transpose conflict-free
    __shared__ float Ws[16][256];
    int tid = threadIdx.x;
    int m0 = blockIdx.x * 64;
    int tx = tid & 31, ty = tid >> 5;
    int am = tid >> 2;
    int ak = (tid & 3) * 4;
    int wk = tid >> 4;
    int wf = tid & 15;

    float acc[8][8];
#pragma unroll
    for (int i = 0; i < 8; i++)
#pragma unroll
        for (int j = 0; j < 8; j++) acc[i][j] = 0.f;

    for (int k0 = 0; k0 < K; k0 += 16) {
        float4 av = make_float4(0.f, 0.f, 0.f, 0.f);
        if (m0 + am < M)
            av = *(const float4*)(A + (size_t)(m0 + am) * K + k0 + ak);
        As[ak + 0][am] = av.x;
        As[ak + 1][am] = av.y;
        As[ak + 2][am] = av.z;
        As[ak + 3][am] = av.w;
        const float4* Wr = (const float4*)(W + (size_t)(k0 + wk) * 256);
        float4* Wsr = (float4*)(&Ws[wk][0]);
#pragma unroll
        for (int j = 0; j < 4; j++) Wsr[wf + j * 16] = Wr[wf + j * 16];
        __syncthreads();
#pragma unroll
        for (int k = 0; k < 16; k++) {
            float a[8];
#pragma unroll
            for (int i = 0; i < 8; i++) a[i] = As[k][ty * 8 + i];
            float4 w0 = ((float4*)&Ws[k][0])[tx * 2];
            float4 w1 = ((float4*)&Ws[k][0])[tx * 2 + 1];
            float w[8] = {w0.x, w0.y, w0.z, w0.w, w1.x, w1.y, w1.z, w1.w};
#pragma unroll
            for (int i = 0; i < 8; i++)
#pragma unroll
                for (int j = 0; j < 8; j++) acc[i][j] += a[i] * w[j];
        }
        __syncthreads();
    }
#pragma unroll
    for (int i = 0; i < 8; i++) {
        int m = m0 + ty * 8 + i;
        if (m < M) {
            float4* Yr = (float4*)(Y + (size_t)m * 256);
            Yr[tx * 2]     = make_float4(acc[i][0], acc[i][1], acc[i][2], acc[i][3]);
            Yr[tx * 2 + 1] = make_float4(acc[i][4], acc[i][5], acc[i][6], acc[i][7]);
        }
    }
}

// ---------------- scatter-aggregate (warp per node, CSR gather) ----------------

template <int F, bool RELU>
__global__ __launch_bounds__(256) void agg_kernel(int selY, int selH,
                                                  const float* __restrict__ bias) {
    const float* Y = bufsel(selY);
    float* H = bufsel(selH);
    int warp = (blockIdx.x * blockDim.x + threadIdx.x) >> 5;
    int lane = threadIdx.x & 31;
    if (warp >= NN) return;
    const int v = warp;
    const int S = F / 4;  // row stride in float4
    const float4* Y4 = (const float4*)Y;
    const float4* B4 = (const float4*)bias;

    float4 acc0 = B4[lane];
    float4 acc1 = make_float4(0.f, 0.f, 0.f, 0.f);
    if (F == 256) acc1 = B4[32 + lane];

    // self loop: dinv[v]^2 * Y[v]
    float dv = g_dinv[v];
    float w = dv * dv;
    {
        float4 y0 = Y4[(size_t)v * S + lane];
        acc0.x += w * y0.x; acc0.y += w * y0.y;
        acc0.z += w * y0.z; acc0.w += w * y0.w;
        if (F == 256) {
            float4 y1 = Y4[(size_t)v * S + 32 + lane];
            acc1.x += w * y1.x; acc1.y += w * y1.y;
            acc1.z += w * y1.z; acc1.w += w * y1.w;
        }
    }

    int e0 = g_off[v], e1 = g_off[v + 1];
    for (int e = e0; e < e1; e++) {
        int s = g_csr_src[e];
        float nrm = g_csr_norm[e];
        float4 a = Y4[(size_t)s * S + lane];
        acc0.x += nrm * a.x; acc0.y += nrm * a.y;
        acc0.z += nrm * a.z; acc0.w += nrm * a.w;
        if (F == 256) {
            float4 b = Y4[(size_t)s * S + 32 + lane];
            acc1.x += nrm * b.x; acc1.y += nrm * b.y;
            acc1.z += nrm * b.z; acc1.w += nrm * b.w;
        }
    }

    if (RELU) {
        acc0.x = fmaxf(acc0.x, 0.f); acc0.y = fmaxf(acc0.y, 0.f);
        acc0.z = fmaxf(acc0.z, 0.f); acc0.w = fmaxf(acc0.w, 0.f);
        if (F == 256) {
            acc1.x = fmaxf(acc1.x, 0.f); acc1.y = fmaxf(acc1.y, 0.f);
            acc1.z = fmaxf(acc1.z, 0.f); acc1.w = fmaxf(acc1.w, 0.f);
        }
    }
    float4* H4 = (float4*)H;
    H4[(size_t)v * S + lane] = acc0;
    if (F == 256) H4[(size_t)v * S + 32 + lane] = acc1;
}

// ---------------- global max pool ----------------------------------------------

__global__ void pool_init_kernel() {
    int i = blockIdx.x * blockDim.x + threadIdx.x;
    if (i < NG * 256) g_pool[i] = -INFINITY;
}

__device__ __forceinline__ void atomicMaxF(float* a, float v) {
    if (v >= 0.f) atomicMax((int*)a, __float_as_int(v));
    else          atomicMin((unsigned int*)a, __float_as_uint(v));
}

__global__ __launch_bounds__(256) void pool_kernel(const int* __restrict__ batch) {
    const float* H = g_bufC;
    int f = threadIdx.x;                 // 0..255 feature
    int v0 = blockIdx.x * 64;
    int vend = min(v0 + 64, NN);
    if (v0 >= NN) return;
    float m = -INFINITY;
    int cg = batch[v0];
    for (int v = v0; v < vend; v++) {
        int g = batch[v];
        if (g != cg) {
            atomicMaxF(&g_pool[cg * 256 + f], m);
            m = -INFINITY;
            cg = g;
        }
        m = fmaxf(m, H[(size_t)v * 256 + f]);
    }
    atomicMaxF(&g_pool[cg * 256 + f], m);
}

// ---------------- dense head ----------------------------------------------------

__global__ __launch_bounds__(128) void head_kernel(const float* __restrict__ Wl2,
                                                   const float* __restrict__ bl2,
                                                   const float* __restrict__ Wl3,
                                                   const float* __restrict__ bl3,
                                                   const float* __restrict__ Wl,
                                                   const float* __restrict__ bl,
                                                   float* __restrict__ out) {
    __shared__ float gs[256];
    __shared__ float h2[128];
    __shared__ float h3[128];
    int g = blockIdx.x;
    int t = threadIdx.x;
    gs[t]       = g_pool[g * 256 + t];
    gs[t + 128] = g_pool[g * 256 + 128 + t];
    __syncthreads();
    float a = bl2[t];
    for (int k = 0; k < 256; k++) a += gs[k] * Wl2[k * 128 + t];
    h2[t] = fmaxf(a, 0.f);
    __syncthreads();
    float b = bl3[t];
    for (int k = 0; k < 128; k++) b += h2[k] * Wl3[k * 128 + t];
    h3[t] = fmaxf(b, 0.f);
    __syncthreads();
    if (t < 10) {
        float c = bl[t];
        for (int k = 0; k < 128; k++) c += h3[k] * Wl[k * 10 + t];
        out[g * 10 + t] = c;
    }
}

// ---------------- launch ---------------------------------------------------------

extern "C" void kernel_launch(void* const* d_in, const int* in_sizes, int n_in,
                              void* d_out, int out_size) {
    const float* x     = (const float*)d_in[0];
    const int*   ei    = (const int*)d_in[1];     // [2,E] int32 (JAX x64 disabled)
    const int*   batch = (const int*)d_in[2];
    const float *W1 = (const float*)d_in[3],  *b1 = (const float*)d_in[4];
    const float *W2 = (const float*)d_in[5],  *b2 = (const float*)d_in[6];
    const float *W3 = (const float*)d_in[7],  *b3 = (const float*)d_in[8];
    const float *W4 = (const float*)d_in[9],  *b4 = (const float*)d_in[10];
    const float *Wl2 = (const float*)d_in[11], *bl2 = (const float*)d_in[12];
    const float *Wl3 = (const float*)d_in[13], *bl3 = (const float*)d_in[14];
    const float *Wl  = (const float*)d_in[15], *bl  = (const float*)d_in[16];
    float* out = (float*)d_out;

    const int* esrc = ei;
    const int* edst = ei + NE;

    // preprocessing: degrees, scan, CSR by dst
    zero_cnt_kernel<<<(NN + 255) / 256, 256>>>();
    count_kernel<<<(NE + 255) / 256, 256>>>(edst);
    scan_kernel<<<1, 1024>>>();
    dinv_cur_kernel<<<(NN + 255) / 256, 256>>>();
    fill_kernel<<<(NE + 255) / 256, 256>>>(esrc, edst);

    const int AGG_GRID = (NN + 7) / 8;   // 8 warps/block, warp per node
    const int GEMM_GRID = (NN + 63) / 64;

    // buffers: 0=g_bufA, 1=g_bufB, 2=g_bufC
    // layer 1: K=9 -> F=128 (writes buf 1)
    gemm_k9<<<NN / 2, 256>>>(x, W1);
    agg_kernel<128, true><<<AGG_GRID, 256>>>(1, 0, b1);
    // layer 2: K=128 -> F=256
    gemm_f256<<<GEMM_GRID, 256>>>(0, 1, W2, NN, 128);
    agg_kernel<256, true><<<AGG_GRID, 256>>>(1, 2, b2);
    // layer 3: K=256 -> F=256
    gemm_f256<<<GEMM_GRID, 256>>>(2, 1, W3, NN, 256);
    agg_kernel<256, true><<<AGG_GRID, 256>>>(1, 0, b3);
    // layer 4: K=256 -> F=256 (no relu)
    gemm_f256<<<GEMM_GRID, 256>>>(0, 1, W4, NN, 256);
    agg_kernel<256, false><<<AGG_GRID, 256>>>(1, 2, b4);

    // global max pool + head (pool reads g_bufC = sel 2)
    pool_init_kernel<<<(NG * 256 + 255) / 256, 256>>>();
    pool_kernel<<<(NN + 63) / 64, 256>>>(batch);
    head_kernel<<<NG, 128>>>(Wl2, bl2, Wl3, bl3, Wl, bl, out);
}

// round 4
// speedup vs baseline: 1.1817x; 1.1817x over previous
#include <cuda_runtime.h>
#include <math.h>

#define NN 50000
#define NE 800000
#define NG 64
#define SCAN_B ((NN + 255) / 256)

typedef unsigned long long u64;

// ---------------- scratch (device globals; no allocation allowed) -------------
__device__ float g_bufA[NN * 256];
__device__ float g_bufB[NN * 256];
__device__ float g_bufC[NN * 256];
__device__ float g_dinv[NN];
__device__ int   g_cnt[NN];
__device__ int   g_off[NN + 1];
__device__ int   g_cur[NN];
__device__ int   g_bsum[SCAN_B];
__device__ int   g_csr_src[NE];
__device__ float g_csr_norm[NE];
__device__ float g_pool[NG * 256];

__device__ __forceinline__ float* bufsel(int s) {
    return (s == 0) ? g_bufA : (s == 1) ? g_bufB : g_bufC;
}

// f32x2 packed helpers (Blackwell FFMA2 path)
__device__ __forceinline__ u64 pack2(float lo, float hi) {
    u64 r;
    asm("mov.b64 %0, {%1, %2};" : "=l"(r) : "f"(lo), "f"(hi));
    return r;
}
__device__ __forceinline__ void fma2(u64& acc, u64 a, u64 b) {
    asm("fma.rn.f32x2 %0, %1, %2, %0;" : "+l"(acc) : "l"(a), "l"(b));
}
__device__ __forceinline__ float2 unpack2(u64 v) {
    float2 r;
    asm("mov.b64 {%0, %1}, %2;" : "=f"(r.x), "=f"(r.y) : "l"(v));
    return r;
}

// ---------------- preprocessing ----------------------------------------------

__global__ void zero_cnt_kernel() {
    int i = blockIdx.x * blockDim.x + threadIdx.x;
    if (i < NN) g_cnt[i] = 0;
}

__global__ void count_kernel(const int* __restrict__ dst) {
    int e = blockIdx.x * blockDim.x + threadIdx.x;
    if (e < NE) atomicAdd(&g_cnt[dst[e]], 1);
}

// block-local exclusive scan + block totals
__global__ void scan1_kernel() {
    __shared__ int s[256];
    int tid = threadIdx.x;
    int idx = blockIdx.x * 256 + tid;
    int v = (idx < NN) ? g_cnt[idx] : 0;
    s[tid] = v;
    __syncthreads();
#pragma unroll
    for (int o = 1; o < 256; o <<= 1) {
        int t = (tid >= o) ? s[tid - o] : 0;
        __syncthreads();
        s[tid] += t;
        __syncthreads();
    }
    if (idx < NN) g_off[idx] = s[tid] - v;
    if (tid == 255) g_bsum[blockIdx.x] = s[255];
}

// exclusive scan of block totals (single small block)
__global__ void scan2_kernel() {
    __shared__ int s[256];
    int tid = threadIdx.x;
    int v = (tid < SCAN_B) ? g_bsum[tid] : 0;
    s[tid] = v;
    __syncthreads();
#pragma unroll
    for (int o = 1; o < 256; o <<= 1) {
        int t = (tid >= o) ? s[tid - o] : 0;
        __syncthreads();
        s[tid] += t;
        __syncthreads();
    }
    if (tid < SCAN_B) g_bsum[tid] = s[tid] - v;
}

// add block bases, init cur/dinv, set sentinel
__global__ void finalize_kernel() {
    int v = blockIdx.x * blockDim.x + threadIdx.x;
    if (v < NN) {
        int off = g_off[v] + g_bsum[v >> 8];
        g_off[v] = off;
        g_cur[v] = off;
        g_dinv[v] = rsqrtf((float)g_cnt[v] + 1.0f);  // +1 self loop
    }
    if (v == 0) g_off[NN] = NE;
}

__global__ void fill_kernel(const int* __restrict__ src,
                            const int* __restrict__ dst) {
    int e = blockIdx.x * blockDim.x + threadIdx.x;
    if (e < NE) {
        int s = src[e];
        int d = dst[e];
        int pos = atomicAdd(&g_cur[d], 1);
        g_csr_src[pos] = s;
        g_csr_norm[pos] = g_dinv[s] * g_dinv[d];
    }
}

// ---------------- aggregation kernels (aggregate-first order) -----------------

// F=9 aggregation of raw x: warp per node, lanes 0..8 active
__global__ __launch_bounds__(256) void agg9_kernel(const float* __restrict__ x) {
    float* out = g_bufA;
    int warp = (blockIdx.x * blockDim.x + threadIdx.x) >> 5;
    int lane = threadIdx.x & 31;
    if (warp >= NN) return;
    const int v = warp;
    float dv = g_dinv[v];
    float acc = 0.f;
    if (lane < 9) acc = dv * dv * x[v * 9 + lane];
    int e0 = g_off[v], e1 = g_off[v + 1];
    for (int e = e0; e < e1; e++) {
        int s = g_csr_src[e];          // broadcast load
        float nrm = g_csr_norm[e];
        if (lane < 9) acc += nrm * x[s * 9 + lane];
    }
    if (lane < 9) out[v * 9 + lane] = acc;
}

// generic F=128/256 aggregation (warp per node, pure gather-sum, no bias/relu)
template <int F>
__global__ __launch_bounds__(256) void agg_kernel(int selY, int selH) {
    const float* Y = bufsel(selY);
    float* H = bufsel(selH);
    int warp = (blockIdx.x * blockDim.x + threadIdx.x) >> 5;
    int lane = threadIdx.x & 31;
    if (warp >= NN) return;
    const int v = warp;
    const int S = F / 4;
    const float4* Y4 = (const float4*)Y;

    float dv = g_dinv[v];
    float w = dv * dv;
    float4 acc0, acc1;
    {
        float4 y0 = Y4[(size_t)v * S + lane];
        acc0 = make_float4(w * y0.x, w * y0.y, w * y0.z, w * y0.w);
        if (F == 256) {
            float4 y1 = Y4[(size_t)v * S + 32 + lane];
            acc1 = make_float4(w * y1.x, w * y1.y, w * y1.z, w * y1.w);
        }
    }

    int e0 = g_off[v], e1 = g_off[v + 1];
    for (int e = e0; e < e1; e++) {
        int s = g_csr_src[e];
        float nrm = g_csr_norm[e];
        float4 a = Y4[(size_t)s * S + lane];
        acc0.x += nrm * a.x; acc0.y += nrm * a.y;
        acc0.z += nrm * a.z; acc0.w += nrm * a.w;
        if (F == 256) {
            float4 b = Y4[(size_t)s * S + 32 + lane];
            acc1.x += nrm * b.x; acc1.y += nrm * b.y;
            acc1.z += nrm * b.z; acc1.w += nrm * b.w;
        }
    }

    float4* H4 = (float4*)H;
    H4[(size_t)v * S + lane] = acc0;
    if (F == 256) H4[(size_t)v * S + 32 + lane] = acc1;
}

// ---------------- GEMMs --------------------------------------------------------

// layer 1: [N,9] @ [9,128] + bias + relu  (reads g_bufA, writes g_bufB)
__global__ __launch_bounds__(256) void gemm_k9(const float* __restrict__ W,
                                               const float* __restrict__ bias) {
    const float* xa = g_bufA;
    __shared__ float Ws[9 * 128];
    __shared__ float Bs[128];
    int tid = threadIdx.x;
    for (int i = tid; i < 9 * 128; i += 256) Ws[i] = W[i];
    if (tid < 128) Bs[tid] = bias[tid];
    __syncthreads();
    int v = blockIdx.x * 2 + (tid >> 7);
    int f = tid & 127;
    if (v < NN) {
        float acc = Bs[f];
#pragma unroll
        for (int k = 0; k < 9; k++) acc += xa[v * 9 + k] * Ws[k * 128 + f];
        g_bufB[v * 128 + f] = fmaxf(acc, 0.f);
    }
}

// [M,K] @ [K,256] fp32 with packed FFMA2; BM=64, BN=256, BK=16, 8x8/thread
// epilogue: + bias, optional relu
template <bool RELU>
__global__ __launch_bounds__(256) void gemm_f256(int selA, int selY,
                                                 const float* __restrict__ W,
                                                 const float* __restrict__ bias,
                                                 int K) {
    const float* A = bufsel(selA);
    float* Y = bufsel(selY);
    const int M = NN;
    __shared__ float As[16][66];   // padded -> STS-transpose conflict-free
    __shared__ float Ws[16][256];
    int tid = threadIdx.x;
    int m0 = blockIdx.x * 64;
    int tx = tid & 31, ty = tid >> 5;
    int am = tid >> 2;
    int ak = (tid & 3) * 4;
    int wk = tid >> 4;
    int wf = tid & 15;

    u64 acc2[8][4];   // [i][j2]: columns (tx*8 + 2*j2, +1)
#pragma unroll
    for (int i = 0; i < 8; i++)
#pragma unroll
        for (int j = 0; j < 4; j++) acc2[i][j] = pack2(0.f, 0.f);

    for (int k0 = 0; k0 < K; k0 += 16) {
        float4 av = make_float4(0.f, 0.f, 0.f, 0.f);
        if (m0 + am < M)
            av = *(const float4*)(A + (size_t)(m0 + am) * K + k0 + ak);
        As[ak + 0][am] = av.x;
        As[ak + 1][am] = av.y;
        As[ak + 2][am] = av.z;
        As[ak + 3][am] = av.w;
        const float4* Wr = (const float4*)(W + (size_t)(k0 + wk) * 256);
        float4* Wsr = (float4*)(&Ws[wk][0]);
#pragma unroll
        for (int j = 0; j < 4; j++) Wsr[wf + j * 16] = Wr[wf + j * 16];
        __syncthreads();
#pragma unroll
        for (int k = 0; k < 16; k++) {
            float4 w0 = ((float4*)&Ws[k][0])[tx * 2];
            float4 w1 = ((float4*)&Ws[k][0])[tx * 2 + 1];
            u64 w2[4];
            w2[0] = pack2(w0.x, w0.y);
            w2[1] = pack2(w0.z, w0.w);
            w2[2] = pack2(w1.x, w1.y);
            w2[3] = pack2(w1.z, w1.w);
#pragma unroll
            for (int i = 0; i < 8; i++) {
                float a = As[k][ty * 8 + i];
                u64 a2 = pack2(a, a);
                fma2(acc2[i][0], a2, w2[0]);
                fma2(acc2[i][1], a2, w2[1]);
                fma2(acc2[i][2], a2, w2[2]);
                fma2(acc2[i][3], a2, w2[3]);
            }
        }
        __syncthreads();
    }

    // epilogue: bias + optional relu
    float4 bb0 = ((const float4*)bias)[tx * 2];
    float4 bb1 = ((const float4*)bias)[tx * 2 + 1];
    float bb[8] = {bb0.x, bb0.y, bb0.z, bb0.w, bb1.x, bb1.y, bb1.z, bb1.w};
#pragma unroll
    for (int i = 0; i < 8; i++) {
        int m = m0 + ty * 8 + i;
        if (m < M) {
            float o[8];
#pragma unroll
            for (int j = 0; j < 4; j++) {
                float2 u = unpack2(acc2[i][j]);
                o[2 * j]     = u.x + bb[2 * j];
                o[2 * j + 1] = u.y + bb[2 * j + 1];
            }
            if (RELU) {
#pragma unroll
                for (int j = 0; j < 8; j++) o[j] = fmaxf(o[j], 0.f);
            }
            float4* Yr = (float4*)(Y + (size_t)m * 256);
            Yr[tx * 2]     = make_float4(o[0], o[1], o[2], o[3]);
            Yr[tx * 2 + 1] = make_float4(o[4], o[5], o[6], o[7]);
        }
    }
}

// ---------------- global max pool ----------------------------------------------

__global__ void pool_init_kernel() {
    int i = blockIdx.x * blockDim.x + threadIdx.x;
    if (i < NG * 256) g_pool[i] = -INFINITY;
}

__device__ __forceinline__ void atomicMaxF(float* a, float v) {
    if (v >= 0.f) atomicMax((int*)a, __float_as_int(v));
    else          atomicMin((unsigned int*)a, __float_as_uint(v));
}

__global__ __launch_bounds__(256) void pool_kernel(const int* __restrict__ batch) {
    const float* H = g_bufB;
    int f = threadIdx.x;                 // 0..255 feature
    int v0 = blockIdx.x * 64;
    int vend = min(v0 + 64, NN);
    if (v0 >= NN) return;
    float m = -INFINITY;
    int cg = batch[v0];
    for (int v = v0; v < vend; v++) {
        int g = batch[v];
        if (g != cg) {
            atomicMaxF(&g_pool[cg * 256 + f], m);
            m = -INFINITY;
            cg = g;
        }
        m = fmaxf(m, H[(size_t)v * 256 + f]);
    }
    atomicMaxF(&g_pool[cg * 256 + f], m);
}

// ---------------- dense head ----------------------------------------------------

__global__ __launch_bounds__(128) void head_kernel(const float* __restrict__ Wl2,
                                                   const float* __restrict__ bl2,
                                                   const float* __restrict__ Wl3,
                                                   const float* __restrict__ bl3,
                                                   const float* __restrict__ Wl,
                                                   const float* __restrict__ bl,
                                                   float* __restrict__ out) {
    __shared__ float gs[256];
    __shared__ float h2[128];
    __shared__ float h3[128];
    int g = blockIdx.x;
    int t = threadIdx.x;
    gs[t]       = g_pool[g * 256 + t];
    gs[t + 128] = g_pool[g * 256 + 128 + t];
    __syncthreads();
    float a = bl2[t];
    for (int k = 0; k < 256; k++) a += gs[k] * Wl2[k * 128 + t];
    h2[t] = fmaxf(a, 0.f);
    __syncthreads();
    float b = bl3[t];
    for (int k = 0; k < 128; k++) b += h2[k] * Wl3[k * 128 + t];
    h3[t] = fmaxf(b, 0.f);
    __syncthreads();
    if (t < 10) {
        float c = bl[t];
        for (int k = 0; k < 128; k++) c += h3[k] * Wl[k * 10 + t];
        out[g * 10 + t] = c;
    }
}

// ---------------- launch ---------------------------------------------------------

extern "C" void kernel_launch(void* const* d_in, const int* in_sizes, int n_in,
                              void* d_out, int out_size) {
    const float* x     = (const float*)d_in[0];
    const int*   ei    = (const int*)d_in[1];     // [2,E] int32
    const int*   batch = (const int*)d_in[2];
    const float *W1 = (const float*)d_in[3],  *b1 = (const float*)d_in[4];
    const float *W2 = (const float*)d_in[5],  *b2 = (const float*)d_in[6];
    const float *W3 = (const float*)d_in[7],  *b3 = (const float*)d_in[8];
    const float *W4 = (const float*)d_in[9],  *b4 = (const float*)d_in[10];
    const float *Wl2 = (const float*)d_in[11], *bl2 = (const float*)d_in[12];
    const float *Wl3 = (const float*)d_in[13], *bl3 = (const float*)d_in[14];
    const float *Wl  = (const float*)d_in[15], *bl  = (const float*)d_in[16];
    float* out = (float*)d_out;

    const int* esrc = ei;
    const int* edst = ei + NE;

    // preprocessing: degrees, scan, CSR by dst
    zero_cnt_kernel<<<(NN + 255) / 256, 256>>>();
    count_kernel<<<(NE + 255) / 256, 256>>>(edst);
    scan1_kernel<<<SCAN_B, 256>>>();
    scan2_kernel<<<1, 256>>>();
    finalize_kernel<<<(NN + 255) / 256, 256>>>();
    fill_kernel<<<(NE + 255) / 256, 256>>>(esrc, edst);

    const int AGG_GRID = (NN + 7) / 8;   // 8 warps/block, warp per node
    const int GEMM_GRID = (NN + 63) / 64;

    // aggregate-first order: h_l = relu( (Â h_{l-1}) W + b )
    // buffers: 0=A, 1=B, 2=C
    agg9_kernel<<<AGG_GRID, 256>>>(x);                          // x -> A [N,9]
    gemm_k9<<<NN / 2, 256>>>(W1, b1);                           // A -> B [N,128]
    agg_kernel<128><<<AGG_GRID, 256>>>(1, 2);                   // B -> C
    gemm_f256<true><<<GEMM_GRID, 256>>>(2, 0, W2, b2, 128);     // C -> A [N,256]
    agg_kernel<256><<<AGG_GRID, 256>>>(0, 1);                   // A -> B
    gemm_f256<true><<<GEMM_GRID, 256>>>(1, 2, W3, b3, 256);     // B -> C
    agg_kernel<256><<<AGG_GRID, 256>>>(2, 0);                   // C -> A
    gemm_f256<false><<<GEMM_GRID, 256>>>(0, 1, W4, b4, 256);    // A -> B (no relu)

    // global max pool + head (pool reads g_bufB)
    pool_init_kernel<<<(NG * 256 + 255) / 256, 256>>>();
    pool_kernel<<<(NN + 63) / 64, 256>>>(batch);
    head_kernel<<<NG, 128>>>(Wl2, bl2, Wl3, bl3, Wl, bl, out);
}

// round 7
// speedup vs baseline: 1.6506x; 1.3968x over previous
#include <cuda_runtime.h>
#include <cuda_bf16.h>
#include <math.h>

#define NN 50000
#define NE 800000
#define NG 64
#define SCAN_B ((NN + 255) / 256)
#define TM ((NN + 127) / 128)   // 391 m-tiles

typedef unsigned long long u64;
typedef unsigned int u32;

// ---------------- scratch (device globals; no allocation allowed) -------------
__device__ float g_bufA[NN * 256];
__device__ float g_bufB[NN * 256];
__device__ float g_bufC[NN * 256];
__device__ float g_dinv[NN];
__device__ int   g_cnt[NN];
__device__ int   g_off[NN + 1];
__device__ int   g_cur[NN];
__device__ int   g_bsum[SCAN_B];
__device__ int   g_csr_src[NE];
__device__ float g_csr_norm[NE];
__device__ float g_pool[NG * 256];
// bf16 hi/lo operands, flat row-major [NN][K]
__device__ unsigned short g_Ahi[(size_t)NN * 256];
__device__ unsigned short g_Alo[(size_t)NN * 256];
__device__ unsigned short g_Bhi[256 * 256];
__device__ unsigned short g_Blo[256 * 256];

__device__ __forceinline__ float* bufsel(int s) {
    return (s == 0) ? g_bufA : (s == 1) ? g_bufB : g_bufC;
}

// ---------------- PTX helpers ---------------------------------------------------

__device__ __forceinline__ u32 smem_u32(const void* p) {
    u32 a;
    asm("{ .reg .u64 t; cvta.to.shared.u64 t, %1; cvt.u32.u64 %0, t; }" : "=r"(a) : "l"(p));
    return a;
}
__device__ __forceinline__ void ldmx4(u32* r, u32 a) {
    asm volatile("ldmatrix.sync.aligned.m8n8.x4.shared.b16 {%0,%1,%2,%3}, [%4];"
                 : "=r"(r[0]), "=r"(r[1]), "=r"(r[2]), "=r"(r[3]) : "r"(a));
}
__device__ __forceinline__ void ldmx4t(u32* r, u32 a) {
    asm volatile("ldmatrix.sync.aligned.m8n8.x4.trans.shared.b16 {%0,%1,%2,%3}, [%4];"
                 : "=r"(r[0]), "=r"(r[1]), "=r"(r[2]), "=r"(r[3]) : "r"(a));
}
__device__ __forceinline__ void mma16816(float* c, const u32* a, const u32* b) {
    asm volatile(
        "mma.sync.aligned.m16n8k16.row.col.f32.bf16.bf16.f32 "
        "{%0,%1,%2,%3}, {%4,%5,%6,%7}, {%8,%9}, {%0,%1,%2,%3};"
        : "+f"(c[0]), "+f"(c[1]), "+f"(c[2]), "+f"(c[3])
        : "r"(a[0]), "r"(a[1]), "r"(a[2]), "r"(a[3]), "r"(b[0]), "r"(b[1]));
}

__device__ __forceinline__ u32 pack_hilo(float a, float b, int lo) {
    __nv_bfloat16 ha = __float2bfloat16(a);
    __nv_bfloat16 hb = __float2bfloat16(b);
    if (lo) {
        ha = __float2bfloat16(a - __bfloat162float(ha));
        hb = __float2bfloat16(b - __bfloat162float(hb));
    }
    return (u32)__bfloat16_as_ushort(ha) | ((u32)__bfloat16_as_ushort(hb) << 16);
}

// ---------------- preprocessing ----------------------------------------------

__global__ void zero_cnt_kernel() {
    int i = blockIdx.x * blockDim.x + threadIdx.x;
    if (i < NN) g_cnt[i] = 0;
}

__global__ void count_kernel(const int* __restrict__ dst) {
    int e = blockIdx.x * blockDim.x + threadIdx.x;
    if (e < NE) atomicAdd(&g_cnt[dst[e]], 1);
}

__global__ void scan1_kernel() {
    __shared__ int s[256];
    int tid = threadIdx.x;
    int idx = blockIdx.x * 256 + tid;
    int v = (idx < NN) ? g_cnt[idx] : 0;
    s[tid] = v;
    __syncthreads();
#pragma unroll
    for (int o = 1; o < 256; o <<= 1) {
        int t = (tid >= o) ? s[tid - o] : 0;
        __syncthreads();
        s[tid] += t;
        __syncthreads();
    }
    if (idx < NN) g_off[idx] = s[tid] - v;
    if (tid == 255) g_bsum[blockIdx.x] = s[255];
}

__global__ void scan2_kernel() {
    __shared__ int s[256];
    int tid = threadIdx.x;
    int v = (tid < SCAN_B) ? g_bsum[tid] : 0;
    s[tid] = v;
    __syncthreads();
#pragma unroll
    for (int o = 1; o < 256; o <<= 1) {
        int t = (tid >= o) ? s[tid - o] : 0;
        __syncthreads();
        s[tid] += t;
        __syncthreads();
    }
    if (tid < SCAN_B) g_bsum[tid] = s[tid] - v;
}

__global__ void finalize_kernel() {
    int v = blockIdx.x * blockDim.x + threadIdx.x;
    if (v < NN) {
        int off = g_off[v] + g_bsum[v >> 8];
        g_off[v] = off;
        g_cur[v] = off;
        g_dinv[v] = rsqrtf((float)g_cnt[v] + 1.0f);
    }
    if (v == 0) g_off[NN] = NE;
}

__global__ void fill_kernel(const int* __restrict__ src,
                            const int* __restrict__ dst) {
    int e = blockIdx.x * blockDim.x + threadIdx.x;
    if (e < NE) {
        int s = src[e];
        int d = dst[e];
        int pos = atomicAdd(&g_cur[d], 1);
        g_csr_src[pos] = s;
        g_csr_norm[pos] = g_dinv[s] * g_dinv[d];
    }
}

// ---------------- aggregation kernels ------------------------------------------

// F=9 aggregation of raw x -> g_bufC [N,9] fp32
__global__ __launch_bounds__(256) void agg9_kernel(const float* __restrict__ x) {
    float* out = g_bufC;
    int warp = (blockIdx.x * blockDim.x + threadIdx.x) >> 5;
    int lane = threadIdx.x & 31;
    if (warp >= NN) return;
    const int v = warp;
    float dv = g_dinv[v];
    float acc = 0.f;
    if (lane < 9) acc = dv * dv * x[v * 9 + lane];
    int e0 = g_off[v], e1 = g_off[v + 1];
    for (int e = e0; e < e1; e++) {
        int s = g_csr_src[e];
        float nrm = g_csr_norm[e];
        if (lane < 9) acc += nrm * x[s * 9 + lane];
    }
    if (lane < 9) out[v * 9 + lane] = acc;
}

// F=128/256 aggregation: gather fp32 rows, emit hi/lo bf16 flat [NN][F]
template <int F>
__global__ __launch_bounds__(256) void agg_hilo(int selY) {
    const float* Y = bufsel(selY);
    int warp = (blockIdx.x * blockDim.x + threadIdx.x) >> 5;
    int lane = threadIdx.x & 31;
    if (warp >= NN) return;
    const int v = warp;
    const int S = F / 4;
    const float4* Y4 = (const float4*)Y;

    float dv = g_dinv[v];
    float w = dv * dv;
    float acc[F / 32];
    if (F == 256) {
        float4 p0 = Y4[(size_t)v * S + 2 * lane];
        float4 p1 = Y4[(size_t)v * S + 2 * lane + 1];
        acc[0] = w * p0.x; acc[1] = w * p0.y; acc[2] = w * p0.z; acc[3] = w * p0.w;
        acc[4] = w * p1.x; acc[5] = w * p1.y; acc[6] = w * p1.z; acc[7] = w * p1.w;
    } else {
        float4 p0 = Y4[(size_t)v * S + lane];
        acc[0] = w * p0.x; acc[1] = w * p0.y; acc[2] = w * p0.z; acc[3] = w * p0.w;
    }

    int e0 = g_off[v], e1 = g_off[v + 1];
    for (int e = e0; e < e1; e++) {
        int s = g_csr_src[e];
        float nrm = g_csr_norm[e];
        if (F == 256) {
            float4 q0 = Y4[(size_t)s * S + 2 * lane];
            float4 q1 = Y4[(size_t)s * S + 2 * lane + 1];
            acc[0] += nrm * q0.x; acc[1] += nrm * q0.y; acc[2] += nrm * q0.z; acc[3] += nrm * q0.w;
            acc[4] += nrm * q1.x; acc[5] += nrm * q1.y; acc[6] += nrm * q1.z; acc[7] += nrm * q1.w;
        } else {
            float4 q0 = Y4[(size_t)s * S + lane];
            acc[0] += nrm * q0.x; acc[1] += nrm * q0.y; acc[2] += nrm * q0.z; acc[3] += nrm * q0.w;
        }
    }

    if (F == 256) {
        uint4 hi = make_uint4(pack_hilo(acc[0], acc[1], 0), pack_hilo(acc[2], acc[3], 0),
                              pack_hilo(acc[4], acc[5], 0), pack_hilo(acc[6], acc[7], 0));
        uint4 lo = make_uint4(pack_hilo(acc[0], acc[1], 1), pack_hilo(acc[2], acc[3], 1),
                              pack_hilo(acc[4], acc[5], 1), pack_hilo(acc[6], acc[7], 1));
        ((uint4*)g_Ahi)[(size_t)v * 32 + lane] = hi;
        ((uint4*)g_Alo)[(size_t)v * 32 + lane] = lo;
    } else {
        uint2 hi = make_uint2(pack_hilo(acc[0], acc[1], 0), pack_hilo(acc[2], acc[3], 0));
        uint2 lo = make_uint2(pack_hilo(acc[0], acc[1], 1), pack_hilo(acc[2], acc[3], 1));
        ((uint2*)g_Ahi)[(size_t)v * 32 + lane] = hi;
        ((uint2*)g_Alo)[(size_t)v * 32 + lane] = lo;
    }
}

// weight conversion: W[K,256] fp32 -> g_Bhi/g_Blo [K][256] bf16 (same layout)
__global__ void conv_w_kernel(const float* __restrict__ W, int K) {
    int i = blockIdx.x * 256 + threadIdx.x;
    if (i >= 256 * K) return;
    float v = W[i];
    __nv_bfloat16 h = __float2bfloat16(v);
    __nv_bfloat16 l = __float2bfloat16(v - __bfloat162float(h));
    g_Bhi[i] = __bfloat16_as_ushort(h);
    g_Blo[i] = __bfloat16_as_ushort(l);
}

// ---------------- layer-1 GEMM (tiny K) -----------------------------------------

// [N,9] @ [9,128] + bias + relu  (reads g_bufC, writes g_bufA)
__global__ __launch_bounds__(256) void gemm_k9(const float* __restrict__ W,
                                               const float* __restrict__ bias) {
    const float* xa = g_bufC;
    __shared__ float Ws[9 * 128];
    __shared__ float Bs[128];
    int tid = threadIdx.x;
    for (int i = tid; i < 9 * 128; i += 256) Ws[i] = W[i];
    if (tid < 128) Bs[tid] = bias[tid];
    __syncthreads();
    int v = blockIdx.x * 2 + (tid >> 7);
    int f = tid & 127;
    if (v < NN) {
        float acc = Bs[f];
#pragma unroll
        for (int k = 0; k < 9; k++) acc += xa[v * 9 + k] * Ws[k * 128 + f];
        g_bufA[v * 128 + f] = fmaxf(acc, 0.f);
    }
}

// ---------------- mma.sync bf16x3 GEMM: [N,K] @ [K,256] + bias (+relu) ----------
// BM=128, BN=128, BK=32; 8 warps (4x2), warp tile 32x64

#define SA 40    // A smem stride (bf16 elems); 80B rows -> 16B-aligned vec stores
#define SB 136   // B smem stride (272B rows)

__global__ __launch_bounds__(256) void gemm_mma(const float* __restrict__ bias,
                                                int selOut, int relu, int K) {
    __shared__ __align__(16) unsigned short Ah[128 * SA], Al[128 * SA];
    __shared__ __align__(16) unsigned short Bh[32 * SB], Bl[32 * SB];
    __shared__ float bs[128];
    int tid = threadIdx.x, lane = tid & 31, wid = tid >> 5;
    int tm = blockIdx.x, tn = blockIdx.y;
    int wm = wid & 3, wn = wid >> 2;
    if (tid < 128) bs[tid] = bias[tn * 128 + tid];

    float c[16][4];
#pragma unroll
    for (int i = 0; i < 16; i++)
#pragma unroll
        for (int j = 0; j < 4; j++) c[i][j] = 0.f;

    u32 sAh = smem_u32(Ah), sAl = smem_u32(Al);
    u32 sBh = smem_u32(Bh), sBl = smem_u32(Bl);

    for (int k0 = 0; k0 < K; k0 += 32) {
        // A tile: 128 rows x 32 cols, hi+lo
#pragma unroll
        for (int i = 0; i < 2; i++) {
            int idx = tid + i * 256;
            int row = idx >> 2, cg = idx & 3;
            int grow = tm * 128 + row;
            uint4 vh = make_uint4(0, 0, 0, 0), vl = vh;
            if (grow < NN) {
                vh = *(const uint4*)(g_Ahi + (size_t)grow * K + k0 + cg * 8);
                vl = *(const uint4*)(g_Alo + (size_t)grow * K + k0 + cg * 8);
            }
            *(uint4*)(Ah + row * SA + cg * 8) = vh;
            *(uint4*)(Al + row * SA + cg * 8) = vl;
        }
        // B tile: 32 rows x 128 cols, hi+lo
#pragma unroll
        for (int i = 0; i < 2; i++) {
            int idx = tid + i * 256;
            int row = idx >> 4, cg = idx & 15;
            *(uint4*)(Bh + row * SB + cg * 8) =
                *(const uint4*)(g_Bhi + (size_t)(k0 + row) * 256 + tn * 128 + cg * 8);
            *(uint4*)(Bl + row * SB + cg * 8) =
                *(const uint4*)(g_Blo + (size_t)(k0 + row) * 256 + tn * 128 + cg * 8);
        }
        __syncthreads();

#pragma unroll
        for (int ks = 0; ks < 2; ks++) {
            u32 ah[2][4], al[2][4], bh[4][4], bl[4][4];
            int ar = wm * 32 + (lane & 15);
            int ac = ks * 16 + (lane >> 4) * 8;
            ldmx4(ah[0], sAh + (u32)((ar * SA + ac) * 2));
            ldmx4(ah[1], sAh + (u32)(((ar + 16) * SA + ac) * 2));
            ldmx4(al[0], sAl + (u32)((ar * SA + ac) * 2));
            ldmx4(al[1], sAl + (u32)(((ar + 16) * SA + ac) * 2));
            int br = ks * 16 + (lane & 15);
#pragma unroll
            for (int g = 0; g < 4; g++) {
                int bc = wn * 64 + g * 16 + (lane >> 4) * 8;
                ldmx4t(bh[g], sBh + (u32)((br * SB + bc) * 2));
                ldmx4t(bl[g], sBl + (u32)((br * SB + bc) * 2));
            }
#pragma unroll
            for (int mt = 0; mt < 2; mt++)
#pragma unroll
                for (int nt = 0; nt < 8; nt++) {
                    float* cc = c[mt * 8 + nt];
                    const u32* pbh = &bh[nt >> 1][(nt & 1) * 2];
                    const u32* pbl = &bl[nt >> 1][(nt & 1) * 2];
                    mma16816(cc, ah[mt], pbh);
                    mma16816(cc, ah[mt], pbl);
                    mma16816(cc, al[mt], pbh);
                }
        }
        __syncthreads();
    }

    // epilogue: bias + optional relu, fp32 out [NN,256]
    float* Out = bufsel(selOut);
#pragma unroll
    for (int mt = 0; mt < 2; mt++) {
#pragma unroll
        for (int nt = 0; nt < 8; nt++) {
            int r0 = tm * 128 + wm * 32 + mt * 16 + (lane >> 2);
            int cl = wn * 64 + nt * 8 + (lane & 3) * 2;
            int col = tn * 128 + cl;
            float b0 = bs[cl], b1 = bs[cl + 1];
            float v0 = c[mt * 8 + nt][0] + b0;
            float v1 = c[mt * 8 + nt][1] + b1;
            float v2 = c[mt * 8 + nt][2] + b0;
            float v3 = c[mt * 8 + nt][3] + b1;
            if (relu) {
                v0 = fmaxf(v0, 0.f); v1 = fmaxf(v1, 0.f);
                v2 = fmaxf(v2, 0.f); v3 = fmaxf(v3, 0.f);
            }
            if (r0 < NN)
                *(float2*)(Out + (size_t)r0 * 256 + col) = make_float2(v0, v1);
            if (r0 + 8 < NN)
                *(float2*)(Out + (size_t)(r0 + 8) * 256 + col) = make_float2(v2, v3);
        }
    }
}

// ---------------- global max pool ----------------------------------------------

__global__ void pool_init_kernel() {
    int i = blockIdx.x * blockDim.x + threadIdx.x;
    if (i < NG * 256) g_pool[i] = -INFINITY;
}

__device__ __forceinline__ void atomicMaxF(float* a, float v) {
    if (v >= 0.f) atomicMax((int*)a, __float_as_int(v));
    else          atomicMin((unsigned int*)a, __float_as_uint(v));
}

__global__ __launch_bounds__(256) void pool_kernel(const int* __restrict__ batch) {
    const float* H = g_bufB;
    int f = threadIdx.x;
    int v0 = blockIdx.x * 64;
    int vend = min(v0 + 64, NN);
    if (v0 >= NN) return;
    float m = -INFINITY;
    int cg = batch[v0];
    for (int v = v0; v < vend; v++) {
        int g = batch[v];
        if (g != cg) {
            atomicMaxF(&g_pool[cg * 256 + f], m);
            m = -INFINITY;
            cg = g;
        }
        m = fmaxf(m, H[(size_t)v * 256 + f]);
    }
    atomicMaxF(&g_pool[cg * 256 + f], m);
}

// ---------------- dense head ----------------------------------------------------

__global__ __launch_bounds__(128) void head_kernel(const float* __restrict__ Wl2,
                                                   const float* __restrict__ bl2,
                                                   const float* __restrict__ Wl3,
                                                   const float* __restrict__ bl3,
                                                   const float* __restrict__ Wl,
                                                   const float* __restrict__ bl,
                                                   float* __restrict__ out) {
    __shared__ float gs[256];
    __shared__ float h2[128];
    __shared__ float h3[128];
    int g = blockIdx.x;
    int t = threadIdx.x;
    gs[t]       = g_pool[g * 256 + t];
    gs[t + 128] = g_pool[g * 256 + 128 + t];
    __syncthreads();
    float a = bl2[t];
    for (int k = 0; k < 256; k++) a += gs[k] * Wl2[k * 128 + t];
    h2[t] = fmaxf(a, 0.f);
    __syncthreads();
    float b = bl3[t];
    for (int k = 0; k < 128; k++) b += h2[k] * Wl3[k * 128 + t];
    h3[t] = fmaxf(b, 0.f);
    __syncthreads();
    if (t < 10) {
        float c = bl[t];
        for (int k = 0; k < 128; k++) c += h3[k] * Wl[k * 10 + t];
        out[g * 10 + t] = c;
    }
}

// ---------------- launch ---------------------------------------------------------

extern "C" void kernel_launch(void* const* d_in, const int* in_sizes, int n_in,
                              void* d_out, int out_size) {
    const float* x     = (const float*)d_in[0];
    const int*   ei    = (const int*)d_in[1];
    const int*   batch = (const int*)d_in[2];
    const float *W1 = (const float*)d_in[3],  *b1 = (const float*)d_in[4];
    const float *W2 = (const float*)d_in[5],  *b2 = (const float*)d_in[6];
    const float *W3 = (const float*)d_in[7],  *b3 = (const float*)d_in[8];
    const float *W4 = (const float*)d_in[9],  *b4 = (const float*)d_in[10];
    const float *Wl2 = (const float*)d_in[11], *bl2 = (const float*)d_in[12];
    const float *Wl3 = (const float*)d_in[13], *bl3 = (const float*)d_in[14];
    const float *Wl  = (const float*)d_in[15], *bl  = (const float*)d_in[16];
    float* out = (float*)d_out;

    const int* esrc = ei;
    const int* edst = ei + NE;

    // preprocessing
    zero_cnt_kernel<<<(NN + 255) / 256, 256>>>();
    count_kernel<<<(NE + 255) / 256, 256>>>(edst);
    scan1_kernel<<<SCAN_B, 256>>>();
    scan2_kernel<<<1, 256>>>();
    finalize_kernel<<<(NN + 255) / 256, 256>>>();
    fill_kernel<<<(NE + 255) / 256, 256>>>(esrc, edst);

    const int AGG_GRID = (NN + 7) / 8;
    dim3 ggrid(TM, 2);

    // layer 1 (SIMT): agg9 -> bufC ; gemm_k9: bufC -> bufA [N,128]
    agg9_kernel<<<AGG_GRID, 256>>>(x);
    gemm_k9<<<NN / 2, 256>>>(W1, b1);

    // layer 2: agg(bufA,F=128) -> hi/lo ; mma GEMM K=128 -> bufB
    agg_hilo<128><<<AGG_GRID, 256>>>(0);
    conv_w_kernel<<<(256 * 128 + 255) / 256, 256>>>(W2, 128);
    gemm_mma<<<ggrid, 256>>>(b2, 1, 1, 128);

    // layer 3: agg(bufB,F=256) -> hi/lo ; mma GEMM K=256 -> bufA
    agg_hilo<256><<<AGG_GRID, 256>>>(1);
    conv_w_kernel<<<(256 * 256 + 255) / 256, 256>>>(W3, 256);
    gemm_mma<<<ggrid, 256>>>(b3, 0, 1, 256);

    // layer 4: agg(bufA,F=256) -> hi/lo ; mma GEMM K=256 -> bufB (no relu)
    agg_hilo<256><<<AGG_GRID, 256>>>(0);
    conv_w_kernel<<<(256 * 256 + 255) / 256, 256>>>(W4, 256);
    gemm_mma<<<ggrid, 256>>>(b4, 1, 0, 256);

    // pool + head
    pool_init_kernel<<<(NG * 256 + 255) / 256, 256>>>();
    pool_kernel<<<(NN + 63) / 64, 256>>>(batch);
    head_kernel<<<NG, 128>>>(Wl2, bl2, Wl3, bl3, Wl, bl, out);
}

// round 8
// speedup vs baseline: 1.6723x; 1.0132x over previous
#include <cuda_runtime.h>
#include <cuda_bf16.h>
#include <math.h>

#define NN 50000
#define NE 800000
#define NG 64
#define SCAN_B ((NN + 255) / 256)
#define TM ((NN + 127) / 128)   // 391 m-tiles

typedef unsigned long long u64;
typedef unsigned int u32;

// ---------------- scratch (device globals; no allocation allowed) -------------
__device__ float g_bufA[NN * 256];
__device__ float g_bufB[NN * 256];
__device__ float g_bufC[NN * 256];
__device__ float g_dinv[NN];
__device__ int   g_cnt[NN];
__device__ int   g_off[NN + 1];
__device__ int   g_cur[NN];
__device__ int   g_bsum[SCAN_B];
__device__ int   g_csr_src[NE];
__device__ float g_csr_norm[NE];
__device__ float g_pool[NG * 256];
// bf16 hi/lo activations, flat row-major [NN][K]
__device__ unsigned short g_Ahi[(size_t)NN * 256];
__device__ unsigned short g_Alo[(size_t)NN * 256];
// bf16 hi/lo weights per layer (0:W2 K=128, 1:W3, 2:W4)
__device__ unsigned short g_Wh[3][256 * 256];
__device__ unsigned short g_Wl[3][256 * 256];

__device__ __forceinline__ float* bufsel(int s) {
    return (s == 0) ? g_bufA : (s == 1) ? g_bufB : g_bufC;
}

// ---------------- PTX helpers ---------------------------------------------------

__device__ __forceinline__ u32 smem_u32(const void* p) {
    u32 a;
    asm("{ .reg .u64 t; cvta.to.shared.u64 t, %1; cvt.u32.u64 %0, t; }" : "=r"(a) : "l"(p));
    return a;
}
__device__ __forceinline__ void ldmx4(u32* r, u32 a) {
    asm volatile("ldmatrix.sync.aligned.m8n8.x4.shared.b16 {%0,%1,%2,%3}, [%4];"
                 : "=r"(r[0]), "=r"(r[1]), "=r"(r[2]), "=r"(r[3]) : "r"(a));
}
__device__ __forceinline__ void ldmx4t(u32* r, u32 a) {
    asm volatile("ldmatrix.sync.aligned.m8n8.x4.trans.shared.b16 {%0,%1,%2,%3}, [%4];"
                 : "=r"(r[0]), "=r"(r[1]), "=r"(r[2]), "=r"(r[3]) : "r"(a));
}
__device__ __forceinline__ void mma16816(float* c, const u32* a, const u32* b) {
    asm volatile(
        "mma.sync.aligned.m16n8k16.row.col.f32.bf16.bf16.f32 "
        "{%0,%1,%2,%3}, {%4,%5,%6,%7}, {%8,%9}, {%0,%1,%2,%3};"
        : "+f"(c[0]), "+f"(c[1]), "+f"(c[2]), "+f"(c[3])
        : "r"(a[0]), "r"(a[1]), "r"(a[2]), "r"(a[3]), "r"(b[0]), "r"(b[1]));
}
__device__ __forceinline__ void cp16(u32 dst, const void* src, u32 sz) {
    asm volatile("cp.async.cg.shared.global [%0], [%1], 16, %2;"
                 :: "r"(dst), "l"(src), "r"(sz) : "memory");
}
__device__ __forceinline__ void cp_commit() {
    asm volatile("cp.async.commit_group;" ::: "memory");
}
template <int N>
__device__ __forceinline__ void cp_wait() {
    asm volatile("cp.async.wait_group %0;" :: "n"(N) : "memory");
}

__device__ __forceinline__ u32 pack_hilo(float a, float b, int lo) {
    __nv_bfloat16 ha = __float2bfloat16(a);
    __nv_bfloat16 hb = __float2bfloat16(b);
    if (lo) {
        ha = __float2bfloat16(a - __bfloat162float(ha));
        hb = __float2bfloat16(b - __bfloat162float(hb));
    }
    return (u32)__bfloat16_as_ushort(ha) | ((u32)__bfloat16_as_ushort(hb) << 16);
}

// ---------------- preprocessing ----------------------------------------------

__global__ void zero_cnt_kernel() {
    int i = blockIdx.x * blockDim.x + threadIdx.x;
    if (i < NN) g_cnt[i] = 0;
}

__global__ void count_kernel(const int* __restrict__ dst) {
    int e = blockIdx.x * blockDim.x + threadIdx.x;
    if (e < NE) atomicAdd(&g_cnt[dst[e]], 1);
}

__global__ void scan1_kernel() {
    __shared__ int s[256];
    int tid = threadIdx.x;
    int idx = blockIdx.x * 256 + tid;
    int v = (idx < NN) ? g_cnt[idx] : 0;
    s[tid] = v;
    __syncthreads();
#pragma unroll
    for (int o = 1; o < 256; o <<= 1) {
        int t = (tid >= o) ? s[tid - o] : 0;
        __syncthreads();
        s[tid] += t;
        __syncthreads();
    }
    if (idx < NN) g_off[idx] = s[tid] - v;
    if (tid == 255) g_bsum[blockIdx.x] = s[255];
}

__global__ void scan2_kernel() {
    __shared__ int s[256];
    int tid = threadIdx.x;
    int v = (tid < SCAN_B) ? g_bsum[tid] : 0;
    s[tid] = v;
    __syncthreads();
#pragma unroll
    for (int o = 1; o < 256; o <<= 1) {
        int t = (tid >= o) ? s[tid - o] : 0;
        __syncthreads();
        s[tid] += t;
        __syncthreads();
    }
    if (tid < SCAN_B) g_bsum[tid] = s[tid] - v;
}

__global__ void finalize_kernel() {
    int v = blockIdx.x * blockDim.x + threadIdx.x;
    if (v < NN) {
        int off = g_off[v] + g_bsum[v >> 8];
        g_off[v] = off;
        g_cur[v] = off;
        g_dinv[v] = rsqrtf((float)g_cnt[v] + 1.0f);
    }
    if (v == 0) g_off[NN] = NE;
}

__global__ void fill_kernel(const int* __restrict__ src,
                            const int* __restrict__ dst) {
    int e = blockIdx.x * blockDim.x + threadIdx.x;
    if (e < NE) {
        int s = src[e];
        int d = dst[e];
        int pos = atomicAdd(&g_cur[d], 1);
        g_csr_src[pos] = s;
        g_csr_norm[pos] = g_dinv[s] * g_dinv[d];
    }
}

// ---------------- weight conversion (all layers, one launch) -------------------

__global__ void conv_w_all(const float* __restrict__ W2,
                           const float* __restrict__ W3,
                           const float* __restrict__ W4) {
    int i = blockIdx.x * 256 + threadIdx.x;
    const float* W;
    unsigned short *dh, *dl;
    int off;
    if (i < 32768)       { W = W2; off = i;           dh = g_Wh[0]; dl = g_Wl[0]; }
    else if (i < 98304)  { W = W3; off = i - 32768;   dh = g_Wh[1]; dl = g_Wl[1]; }
    else if (i < 163840) { W = W4; off = i - 98304;   dh = g_Wh[2]; dl = g_Wl[2]; }
    else return;
    float v = W[off];
    __nv_bfloat16 h = __float2bfloat16(v);
    __nv_bfloat16 l = __float2bfloat16(v - __bfloat162float(h));
    dh[off] = __bfloat16_as_ushort(h);
    dl[off] = __bfloat16_as_ushort(l);
}

// ---------------- aggregation kernels ------------------------------------------

// F=9 aggregation of raw x -> g_bufC [N,9] fp32
__global__ __launch_bounds__(256) void agg9_kernel(const float* __restrict__ x) {
    float* out = g_bufC;
    int warp = (blockIdx.x * blockDim.x + threadIdx.x) >> 5;
    int lane = threadIdx.x & 31;
    if (warp >= NN) return;
    const int v = warp;
    float dv = g_dinv[v];
    float acc = 0.f;
    if (lane < 9) acc = dv * dv * x[v * 9 + lane];
    int e0 = g_off[v], e1 = g_off[v + 1];
    for (int e = e0; e < e1; e++) {
        int s = g_csr_src[e];
        float nrm = g_csr_norm[e];
        if (lane < 9) acc += nrm * x[s * 9 + lane];
    }
    if (lane < 9) out[v * 9 + lane] = acc;
}

// F=128/256 aggregation: gather fp32 rows (x4 unrolled), emit hi/lo bf16 flat
template <int F>
__global__ __launch_bounds__(256) void agg_hilo(int selY) {
    const float* Y = bufsel(selY);
    int warp = (blockIdx.x * blockDim.x + threadIdx.x) >> 5;
    int lane = threadIdx.x & 31;
    if (warp >= NN) return;
    const int v = warp;
    const int S = F / 4;
    const float4* Y4 = (const float4*)Y;

    float dv = g_dinv[v];
    float w = dv * dv;
    float acc[F / 32];
    if (F == 256) {
        float4 p0 = Y4[(size_t)v * S + 2 * lane];
        float4 p1 = Y4[(size_t)v * S + 2 * lane + 1];
        acc[0] = w * p0.x; acc[1] = w * p0.y; acc[2] = w * p0.z; acc[3] = w * p0.w;
        acc[4] = w * p1.x; acc[5] = w * p1.y; acc[6] = w * p1.z; acc[7] = w * p1.w;
    } else {
        float4 p0 = Y4[(size_t)v * S + lane];
        acc[0] = w * p0.x; acc[1] = w * p0.y; acc[2] = w * p0.z; acc[3] = w * p0.w;
    }

    int e0 = g_off[v], e1 = g_off[v + 1];
    int e = e0;
    for (; e + 4 <= e1; e += 4) {
        int s0 = g_csr_src[e],     s1 = g_csr_src[e + 1];
        int s2 = g_csr_src[e + 2], s3 = g_csr_src[e + 3];
        float n0 = g_csr_norm[e],     n1 = g_csr_norm[e + 1];
        float n2 = g_csr_norm[e + 2], n3 = g_csr_norm[e + 3];
        if (F == 256) {
            float4 a0 = Y4[(size_t)s0 * S + 2 * lane], b0 = Y4[(size_t)s0 * S + 2 * lane + 1];
            float4 a1 = Y4[(size_t)s1 * S + 2 * lane], b1 = Y4[(size_t)s1 * S + 2 * lane + 1];
            float4 a2 = Y4[(size_t)s2 * S + 2 * lane], b2 = Y4[(size_t)s2 * S + 2 * lane + 1];
            float4 a3 = Y4[(size_t)s3 * S + 2 * lane], b3 = Y4[(size_t)s3 * S + 2 * lane + 1];
            acc[0] += n0 * a0.x + n1 * a1.x + n2 * a2.x + n3 * a3.x;
            acc[1] += n0 * a0.y + n1 * a1.y + n2 * a2.y + n3 * a3.y;
            acc[2] += n0 * a0.z + n1 * a1.z + n2 * a2.z + n3 * a3.z;
            acc[3] += n0 * a0.w + n1 * a1.w + n2 * a2.w + n3 * a3.w;
            acc[4] += n0 * b0.x + n1 * b1.x + n2 * b2.x + n3 * b3.x;
            acc[5] += n0 * b0.y + n1 * b1.y + n2 * b2.y + n3 * b3.y;
            acc[6] += n0 * b0.z + n1 * b1.z + n2 * b2.z + n3 * b3.z;
            acc[7] += n0 * b0.w + n1 * b1.w + n2 * b2.w + n3 * b3.w;
        } else {
            float4 a0 = Y4[(size_t)s0 * S + lane];
            float4 a1 = Y4[(size_t)s1 * S + lane];
            float4 a2 = Y4[(size_t)s2 * S + lane];
            float4 a3 = Y4[(size_t)s3 * S + lane];
            acc[0] += n0 * a0.x + n1 * a1.x + n2 * a2.x + n3 * a3.x;
            acc[1] += n0 * a0.y + n1 * a1.y + n2 * a2.y + n3 * a3.y;
            acc[2] += n0 * a0.z + n1 * a1.z + n2 * a2.z + n3 * a3.z;
            acc[3] += n0 * a0.w + n1 * a1.w + n2 * a2.w + n3 * a3.w;
        }
    }
    for (; e < e1; e++) {
        int s = g_csr_src[e];
        float nrm = g_csr_norm[e];
        if (F == 256) {
            float4 q0 = Y4[(size_t)s * S + 2 * lane];
            float4 q1 = Y4[(size_t)s * S + 2 * lane + 1];
            acc[0] += nrm * q0.x; acc[1] += nrm * q0.y; acc[2] += nrm * q0.z; acc[3] += nrm * q0.w;
            acc[4] += nrm * q1.x; acc[5] += nrm * q1.y; acc[6] += nrm * q1.z; acc[7] += nrm * q1.w;
        } else {
            float4 q0 = Y4[(size_t)s * S + lane];
            acc[0] += nrm * q0.x; acc[1] += nrm * q0.y; acc[2] += nrm * q0.z; acc[3] += nrm * q0.w;
        }
    }

    if (F == 256) {
        uint4 hi = make_uint4(pack_hilo(acc[0], acc[1], 0), pack_hilo(acc[2], acc[3], 0),
                              pack_hilo(acc[4], acc[5], 0), pack_hilo(acc[6], acc[7], 0));
        uint4 lo = make_uint4(pack_hilo(acc[0], acc[1], 1), pack_hilo(acc[2], acc[3], 1),
                              pack_hilo(acc[4], acc[5], 1), pack_hilo(acc[6], acc[7], 1));
        ((uint4*)g_Ahi)[(size_t)v * 32 + lane] = hi;
        ((uint4*)g_Alo)[(size_t)v * 32 + lane] = lo;
    } else {
        uint2 hi = make_uint2(pack_hilo(acc[0], acc[1], 0), pack_hilo(acc[2], acc[3], 0));
        uint2 lo = make_uint2(pack_hilo(acc[0], acc[1], 1), pack_hilo(acc[2], acc[3], 1));
        ((uint2*)g_Ahi)[(size_t)v * 32 + lane] = hi;
        ((uint2*)g_Alo)[(size_t)v * 32 + lane] = lo;
    }
}

// ---------------- layer-1 GEMM (tiny K) -----------------------------------------

__global__ __launch_bounds__(256) void gemm_k9(const float* __restrict__ W,
                                               const float* __restrict__ bias) {
    const float* xa = g_bufC;
    __shared__ float Ws[9 * 128];
    __shared__ float Bs[128];
    int tid = threadIdx.x;
    for (int i = tid; i < 9 * 128; i += 256) Ws[i] = W[i];
    if (tid < 128) Bs[tid] = bias[tid];
    __syncthreads();
    int v = blockIdx.x * 2 + (tid >> 7);
    int f = tid & 127;
    if (v < NN) {
        float acc = Bs[f];
#pragma unroll
        for (int k = 0; k < 9; k++) acc += xa[v * 9 + k] * Ws[k * 128 + f];
        g_bufA[v * 128 + f] = fmaxf(acc, 0.f);
    }
}

// ---------------- mma.sync bf16x3 GEMM, cp.async double-buffered ----------------
// BM=128, BN=128, BK=32; 8 warps (4x2), warp tile 32x64

#define SA 40    // A smem stride (bf16 elems); 80B rows
#define SB 136   // B smem stride (272B rows)
#define A_ST (128 * SA)   // shorts per A stage (one of hi/lo)
#define B_ST (32 * SB)
#define GT_SMEM ((2 * 2 * A_ST + 2 * 2 * B_ST) * 2)   // bytes

__global__ __launch_bounds__(256) void gemm_mma(const float* __restrict__ bias,
                                                int selOut, int relu, int K, int wl) {
    extern __shared__ unsigned short smem[];
    unsigned short* Ah = smem;                  // [2][A_ST]
    unsigned short* Al = Ah + 2 * A_ST;
    unsigned short* Bh = Al + 2 * A_ST;         // [2][B_ST]
    unsigned short* Bl = Bh + 2 * B_ST;
    __shared__ float bs[128];

    const unsigned short* GWh = g_Wh[wl];
    const unsigned short* GWl = g_Wl[wl];

    int tid = threadIdx.x, lane = tid & 31, wid = tid >> 5;
    int tm = blockIdx.x, tn = blockIdx.y;
    int wm = wid & 3, wn = wid >> 2;
    if (tid < 128) bs[tid] = bias[tn * 128 + tid];

    float c[16][4];
#pragma unroll
    for (int i = 0; i < 16; i++)
#pragma unroll
        for (int j = 0; j < 4; j++) c[i][j] = 0.f;

    u32 sAh = smem_u32(Ah), sAl = smem_u32(Al);
    u32 sBh = smem_u32(Bh), sBl = smem_u32(Bl);

    // cp.async tile issue for stage st covering K offset k0
    auto issue = [&](int st, int k0) {
        // A: 128 rows x 32 cols hi+lo
#pragma unroll
        for (int i = 0; i < 2; i++) {
            int idx = tid + i * 256;
            int row = idx >> 2, cg = idx & 3;
            int grow = tm * 128 + row;
            u32 sz = (grow < NN) ? 16u : 0u;
            size_t gof = (size_t)grow * K + k0 + cg * 8;
            u32 dof = (u32)((st * A_ST + row * SA + cg * 8) * 2);
            cp16(sAh + dof, g_Ahi + gof, sz);
            cp16(sAl + dof, g_Alo + gof, sz);
        }
        // B: 32 rows x 128 cols hi+lo
#pragma unroll
        for (int i = 0; i < 2; i++) {
            int idx = tid + i * 256;
            int row = idx >> 4, cg = idx & 15;
            size_t gof = (size_t)(k0 + row) * 256 + tn * 128 + cg * 8;
            u32 dof = (u32)((st * B_ST + row * SB + cg * 8) * 2);
            cp16(sBh + dof, GWh + gof, 16u);
            cp16(sBl + dof, GWl + gof, 16u);
        }
        cp_commit();
    };

    const int niter = K >> 5;
    issue(0, 0);
    for (int it = 0; it < niter; it++) {
        int cur = it & 1;
        if (it + 1 < niter) {
            issue((it + 1) & 1, (it + 1) << 5);
            cp_wait<1>();
        } else {
            cp_wait<0>();
        }
        __syncthreads();

        u32 aof = (u32)(cur * A_ST * 2), bof = (u32)(cur * B_ST * 2);
#pragma unroll
        for (int ks = 0; ks < 2; ks++) {
            u32 ah[2][4], al[2][4], bh[4][4], bl[4][4];
            int ar = wm * 32 + (lane & 15);
            int ac = ks * 16 + (lane >> 4) * 8;
            ldmx4(ah[0], sAh + aof + (u32)((ar * SA + ac) * 2));
            ldmx4(ah[1], sAh + aof + (u32)(((ar + 16) * SA + ac) * 2));
            ldmx4(al[0], sAl + aof + (u32)((ar * SA + ac) * 2));
            ldmx4(al[1], sAl + aof + (u32)(((ar + 16) * SA + ac) * 2));
            int br = ks * 16 + (lane & 15);
#pragma unroll
            for (int g = 0; g < 4; g++) {
                int bc = wn * 64 + g * 16 + (lane >> 4) * 8;
                ldmx4t(bh[g], sBh + bof + (u32)((br * SB + bc) * 2));
                ldmx4t(bl[g], sBl + bof + (u32)((br * SB + bc) * 2));
            }
#pragma unroll
            for (int mt = 0; mt < 2; mt++)
#pragma unroll
                for (int nt = 0; nt < 8; nt++) {
                    float* cc = c[mt * 8 + nt];
                    const u32* pbh = &bh[nt >> 1][(nt & 1) * 2];
                    const u32* pbl = &bl[nt >> 1][(nt & 1) * 2];
                    mma16816(cc, ah[mt], pbh);
                    mma16816(cc, ah[mt], pbl);
                    mma16816(cc, al[mt], pbh);
                }
        }
        __syncthreads();
    }

    // epilogue: bias + optional relu, fp32 out [NN,256]
    float* Out = bufsel(selOut);
#pragma unroll
    for (int mt = 0; mt < 2; mt++) {
#pragma unroll
        for (int nt = 0; nt < 8; nt++) {
            int r0 = tm * 128 + wm * 32 + mt * 16 + (lane >> 2);
            int cl = wn * 64 + nt * 8 + (lane & 3) * 2;
            int col = tn * 128 + cl;
            float b0 = bs[cl], b1 = bs[cl + 1];
            float v0 = c[mt * 8 + nt][0] + b0;
            float v1 = c[mt * 8 + nt][1] + b1;
            float v2 = c[mt * 8 + nt][2] + b0;
            float v3 = c[mt * 8 + nt][3] + b1;
            if (relu) {
                v0 = fmaxf(v0, 0.f); v1 = fmaxf(v1, 0.f);
                v2 = fmaxf(v2, 0.f); v3 = fmaxf(v3, 0.f);
            }
            if (r0 < NN)
                *(float2*)(Out + (size_t)r0 * 256 + col) = make_float2(v0, v1);
            if (r0 + 8 < NN)
                *(float2*)(Out + (size_t)(r0 + 8) * 256 + col) = make_float2(v2, v3);
        }
    }
}

// ---------------- global max pool ----------------------------------------------

__global__ void pool_init_kernel() {
    int i = blockIdx.x * blockDim.x + threadIdx.x;
    if (i < NG * 256) g_pool[i] = -INFINITY;
}

__device__ __forceinline__ void atomicMaxF(float* a, float v) {
    if (v >= 0.f) atomicMax((int*)a, __float_as_int(v));
    else          atomicMin((unsigned int*)a, __float_as_uint(v));
}

__global__ __launch_bounds__(256) void pool_kernel(const int* __restrict__ batch) {
    const float* H = g_bufB;
    int f = threadIdx.x;
    int v0 = blockIdx.x * 64;
    int vend = min(v0 + 64, NN);
    if (v0 >= NN) return;
    float m = -INFINITY;
    int cg = batch[v0];
    for (int v = v0; v < vend; v++) {
        int g = batch[v];
        if (g != cg) {
            atomicMaxF(&g_pool[cg * 256 + f], m);
            m = -INFINITY;
            cg = g;
        }
        m = fmaxf(m, H[(size_t)v * 256 + f]);
    }
    atomicMaxF(&g_pool[cg * 256 + f], m);
}

// ---------------- dense head ----------------------------------------------------

__global__ __launch_bounds__(128) void head_kernel(const float* __restrict__ Wl2,
                                                   const float* __restrict__ bl2,
                                                   const float* __restrict__ Wl3,
                                                   const float* __restrict__ bl3,
                                                   const float* __restrict__ Wl,
                                                   const float* __restrict__ bl,
                                                   float* __restrict__ out) {
    __shared__ float gs[256];
    __shared__ float h2[128];
    __shared__ float h3[128];
    int g = blockIdx.x;
    int t = threadIdx.x;
    gs[t]       = g_pool[g * 256 + t];
    gs[t + 128] = g_pool[g * 256 + 128 + t];
    __syncthreads();
    float a = bl2[t];
    for (int k = 0; k < 256; k++) a += gs[k] * Wl2[k * 128 + t];
    h2[t] = fmaxf(a, 0.f);
    __syncthreads();
    float b = bl3[t];
    for (int k = 0; k < 128; k++) b += h2[k] * Wl3[k * 128 + t];
    h3[t] = fmaxf(b, 0.f);
    __syncthreads();
    if (t < 10) {
        float c = bl[t];
        for (int k = 0; k < 128; k++) c += h3[k] * Wl[k * 10 + t];
        out[g * 10 + t] = c;
    }
}

// ---------------- launch ---------------------------------------------------------

extern "C" void kernel_launch(void* const* d_in, const int* in_sizes, int n_in,
                              void* d_out, int out_size) {
    const float* x     = (const float*)d_in[0];
    const int*   ei    = (const int*)d_in[1];
    const int*   batch = (const int*)d_in[2];
    const float *W1 = (const float*)d_in[3],  *b1 = (const float*)d_in[4];
    const float *W2 = (const float*)d_in[5],  *b2 = (const float*)d_in[6];
    const float *W3 = (const float*)d_in[7],  *b3 = (const float*)d_in[8];
    const float *W4 = (const float*)d_in[9],  *b4 = (const float*)d_in[10];
    const float *Wl2 = (const float*)d_in[11], *bl2 = (const float*)d_in[12];
    const float *Wl3 = (const float*)d_in[13], *bl3 = (const float*)d_in[14];
    const float *Wl  = (const float*)d_in[15], *bl  = (const float*)d_in[16];
    float* out = (float*)d_out;

    const int* esrc = ei;
    const int* edst = ei + NE;

    cudaFuncSetAttribute(gemm_mma, cudaFuncAttributeMaxDynamicSharedMemorySize, GT_SMEM);

    // preprocessing + weight conversion (off critical path where possible)
    zero_cnt_kernel<<<(NN + 255) / 256, 256>>>();
    count_kernel<<<(NE + 255) / 256, 256>>>(edst);
    conv_w_all<<<(163840 + 255) / 256, 256>>>(W2, W3, W4);
    scan1_kernel<<<SCAN_B, 256>>>();
    scan2_kernel<<<1, 256>>>();
    finalize_kernel<<<(NN + 255) / 256, 256>>>();
    fill_kernel<<<(NE + 255) / 256, 256>>>(esrc, edst);

    const int AGG_GRID = (NN + 7) / 8;
    dim3 ggrid(TM, 2);

    // layer 1 (SIMT): agg9 -> bufC ; gemm_k9: bufC -> bufA [N,128]
    agg9_kernel<<<AGG_GRID, 256>>>(x);
    gemm_k9<<<NN / 2, 256>>>(W1, b1);

    // layer 2: agg(bufA,F=128) -> hi/lo ; mma GEMM K=128 -> bufB
    agg_hilo<128><<<AGG_GRID, 256>>>(0);
    gemm_mma<<<ggrid, 256, GT_SMEM>>>(b2, 1, 1, 128, 0);

    // layer 3: agg(bufB,F=256) -> hi/lo ; mma GEMM K=256 -> bufA
    agg_hilo<256><<<AGG_GRID, 256>>>(1);
    gemm_mma<<<ggrid, 256, GT_SMEM>>>(b3, 0, 1, 256, 1);

    // layer 4: agg(bufA,F=256) -> hi/lo ; mma GEMM K=256 -> bufB (no relu)
    agg_hilo<256><<<AGG_GRID, 256>>>(0);
    gemm_mma<<<ggrid, 256, GT_SMEM>>>(b4, 1, 0, 256, 2);

    // pool + head
    pool_init_kernel<<<(NG * 256 + 255) / 256, 256>>>();
    pool_kernel<<<(NN + 63) / 64, 256>>>(batch);
    head_kernel<<<NG, 128>>>(Wl2, bl2, Wl3, bl3, Wl, bl, out);
}

// round 9
// speedup vs baseline: 2.1432x; 1.2816x over previous
#include <cuda_runtime.h>
#include <cuda_bf16.h>
#include <cuda_fp16.h>
#include <math.h>

#define NN 50000
#define NE 800000
#define NG 64
#define SCAN_B ((NN + 255) / 256)
#define TM ((NN + 127) / 128)   // 391 m-tiles

typedef unsigned long long u64;
typedef unsigned int u32;

// ---------------- scratch (device globals; no allocation allowed) -------------
__device__ __half g_h16[(size_t)NN * 256];   // layer activations, fp16
__device__ float g_dinv[NN];
__device__ int   g_cnt[NN];
__device__ int   g_off[NN + 1];
__device__ int   g_cur[NN];
__device__ int   g_bsum[SCAN_B];
__device__ int   g_csr_src[NE];
__device__ float g_csr_norm[NE];
__device__ float g_pool[NG * 256];
// bf16 hi/lo GEMM A operand (aggregated activations), flat [NN][K]
__device__ unsigned short g_Ahi[(size_t)NN * 256];
__device__ unsigned short g_Alo[(size_t)NN * 256];
// bf16 hi/lo weights per layer (0:W2 K=128, 1:W3, 2:W4)
__device__ unsigned short g_Wh[3][256 * 256];
__device__ unsigned short g_Wl[3][256 * 256];

// ---------------- PTX helpers ---------------------------------------------------

__device__ __forceinline__ u32 smem_u32(const void* p) {
    u32 a;
    asm("{ .reg .u64 t; cvta.to.shared.u64 t, %1; cvt.u32.u64 %0, t; }" : "=r"(a) : "l"(p));
    return a;
}
__device__ __forceinline__ void ldmx4(u32* r, u32 a) {
    asm volatile("ldmatrix.sync.aligned.m8n8.x4.shared.b16 {%0,%1,%2,%3}, [%4];"
                 : "=r"(r[0]), "=r"(r[1]), "=r"(r[2]), "=r"(r[3]) : "r"(a));
}
__device__ __forceinline__ void ldmx4t(u32* r, u32 a) {
    asm volatile("ldmatrix.sync.aligned.m8n8.x4.trans.shared.b16 {%0,%1,%2,%3}, [%4];"
                 : "=r"(r[0]), "=r"(r[1]), "=r"(r[2]), "=r"(r[3]) : "r"(a));
}
__device__ __forceinline__ void mma16816(float* c, const u32* a, const u32* b) {
    asm volatile(
        "mma.sync.aligned.m16n8k16.row.col.f32.bf16.bf16.f32 "
        "{%0,%1,%2,%3}, {%4,%5,%6,%7}, {%8,%9}, {%0,%1,%2,%3};"
        : "+f"(c[0]), "+f"(c[1]), "+f"(c[2]), "+f"(c[3])
        : "r"(a[0]), "r"(a[1]), "r"(a[2]), "r"(a[3]), "r"(b[0]), "r"(b[1]));
}
__device__ __forceinline__ void cp16(u32 dst, const void* src, u32 sz) {
    asm volatile("cp.async.cg.shared.global [%0], [%1], 16, %2;"
                 :: "r"(dst), "l"(src), "r"(sz) : "memory");
}
__device__ __forceinline__ void cp_commit() {
    asm volatile("cp.async.commit_group;" ::: "memory");
}
template <int N>
__device__ __forceinline__ void cp_wait() {
    asm volatile("cp.async.wait_group %0;" :: "n"(N) : "memory");
}

__device__ __forceinline__ u32 pack_hilo(float a, float b, int lo) {
    __nv_bfloat16 ha = __float2bfloat16(a);
    __nv_bfloat16 hb = __float2bfloat16(b);
    if (lo) {
        ha = __float2bfloat16(a - __bfloat162float(ha));
        hb = __float2bfloat16(b - __bfloat162float(hb));
    }
    return (u32)__bfloat16_as_ushort(ha) | ((u32)__bfloat16_as_ushort(hb) << 16);
}

// ---------------- preprocessing ----------------------------------------------

__global__ void zero_cnt_kernel() {
    int i = blockIdx.x * blockDim.x + threadIdx.x;
    if (i < NN) g_cnt[i] = 0;
}

__global__ void count_kernel(const int* __restrict__ dst) {
    int e = blockIdx.x * blockDim.x + threadIdx.x;
    if (e < NE) atomicAdd(&g_cnt[dst[e]], 1);
}

__global__ void scan1_kernel() {
    __shared__ int s[256];
    int tid = threadIdx.x;
    int idx = blockIdx.x * 256 + tid;
    int v = (idx < NN) ? g_cnt[idx] : 0;
    s[tid] = v;
    __syncthreads();
#pragma unroll
    for (int o = 1; o < 256; o <<= 1) {
        int t = (tid >= o) ? s[tid - o] : 0;
        __syncthreads();
        s[tid] += t;
        __syncthreads();
    }
    if (idx < NN) g_off[idx] = s[tid] - v;
    if (tid == 255) g_bsum[blockIdx.x] = s[255];
}

__global__ void scan2_kernel() {
    __shared__ int s[256];
    int tid = threadIdx.x;
    int v = (tid < SCAN_B) ? g_bsum[tid] : 0;
    s[tid] = v;
    __syncthreads();
#pragma unroll
    for (int o = 1; o < 256; o <<= 1) {
        int t = (tid >= o) ? s[tid - o] : 0;
        __syncthreads();
        s[tid] += t;
        __syncthreads();
    }
    if (tid < SCAN_B) g_bsum[tid] = s[tid] - v;
}

__global__ void finalize_kernel() {
    int v = blockIdx.x * blockDim.x + threadIdx.x;
    if (v < NN) {
        int off = g_off[v] + g_bsum[v >> 8];
        g_off[v] = off;
        g_cur[v] = off;
        g_dinv[v] = rsqrtf((float)g_cnt[v] + 1.0f);
    }
    if (v < NG * 256) g_pool[v] = -INFINITY;   // fused pool init
    if (v == 0) g_off[NN] = NE;
}

__global__ void fill_kernel(const int* __restrict__ src,
                            const int* __restrict__ dst) {
    int e = blockIdx.x * blockDim.x + threadIdx.x;
    if (e < NE) {
        int s = src[e];
        int d = dst[e];
        int pos = atomicAdd(&g_cur[d], 1);
        g_csr_src[pos] = s;
        g_csr_norm[pos] = g_dinv[s] * g_dinv[d];
    }
}

// ---------------- weight conversion (all layers, one launch) -------------------

__global__ void conv_w_all(const float* __restrict__ W2,
                           const float* __restrict__ W3,
                           const float* __restrict__ W4) {
    int i = blockIdx.x * 256 + threadIdx.x;
    const float* W;
    unsigned short *dh, *dl;
    int off;
    if (i < 32768)       { W = W2; off = i;           dh = g_Wh[0]; dl = g_Wl[0]; }
    else if (i < 98304)  { W = W3; off = i - 32768;   dh = g_Wh[1]; dl = g_Wl[1]; }
    else if (i < 163840) { W = W4; off = i - 98304;   dh = g_Wh[2]; dl = g_Wl[2]; }
    else return;
    float v = W[off];
    __nv_bfloat16 h = __float2bfloat16(v);
    __nv_bfloat16 l = __float2bfloat16(v - __bfloat162float(h));
    dh[off] = __bfloat16_as_ushort(h);
    dl[off] = __bfloat16_as_ushort(l);
}

// ---------------- fused layer 1: agg9 + [N,9]@[9,128] + bias + relu -> fp16 -----

__global__ __launch_bounds__(256) void layer1_kernel(const float* __restrict__ x,
                                                     const float* __restrict__ W1,
                                                     const float* __restrict__ b1) {
    __shared__ float Ws[9 * 128];
    __shared__ float Bs[128];
    int tid = threadIdx.x;
    for (int i = tid; i < 9 * 128; i += 256) Ws[i] = W1[i];
    if (tid < 128) Bs[tid] = b1[tid];
    __syncthreads();

    int warp = (blockIdx.x * 256 + tid) >> 5;
    int lane = tid & 31;
    if (warp >= NN) return;
    int v = warp;
    float dv = g_dinv[v];
    float acc = 0.f;
    if (lane < 9) acc = dv * dv * x[v * 9 + lane];
    int e0 = g_off[v], e1 = g_off[v + 1];
    for (int e = e0; e < e1; e++) {
        int s = g_csr_src[e];
        float nrm = g_csr_norm[e];
        if (lane < 9) acc += nrm * x[s * 9 + lane];
    }
    float ak[9];
#pragma unroll
    for (int k = 0; k < 9; k++) ak[k] = __shfl_sync(0xffffffffu, acc, k);

    int f = lane * 4;
    float o0 = Bs[f], o1 = Bs[f + 1], o2 = Bs[f + 2], o3 = Bs[f + 3];
#pragma unroll
    for (int k = 0; k < 9; k++) {
        float a = ak[k];
        const float* wr = &Ws[k * 128 + f];
        o0 += a * wr[0]; o1 += a * wr[1]; o2 += a * wr[2]; o3 += a * wr[3];
    }
    o0 = fmaxf(o0, 0.f); o1 = fmaxf(o1, 0.f);
    o2 = fmaxf(o2, 0.f); o3 = fmaxf(o3, 0.f);
    __half2* dst = (__half2*)(g_h16 + (size_t)v * 128 + f);
    dst[0] = __floats2half2_rn(o0, o1);
    dst[1] = __floats2half2_rn(o2, o3);
}

// ---------------- aggregation: gather fp16 rows, emit hi/lo bf16 flat -----------

template <int F>
__global__ __launch_bounds__(256) void agg_hilo() {
    int warp = (blockIdx.x * blockDim.x + threadIdx.x) >> 5;
    int lane = threadIdx.x & 31;
    if (warp >= NN) return;
    const int v = warp;

    float acc[F / 32];
    float dv = g_dinv[v];
    float w = dv * dv;
    if (F == 256) {
        uint4 q = ((const uint4*)g_h16)[(size_t)v * 32 + lane];
        __half2* h = (__half2*)&q;
#pragma unroll
        for (int j = 0; j < 4; j++) {
            float2 f2 = __half22float2(h[j]);
            acc[2 * j] = w * f2.x; acc[2 * j + 1] = w * f2.y;
        }
    } else {
        uint2 q = ((const uint2*)g_h16)[(size_t)v * 32 + lane];
        __half2* h = (__half2*)&q;
#pragma unroll
        for (int j = 0; j < 2; j++) {
            float2 f2 = __half22float2(h[j]);
            acc[2 * j] = w * f2.x; acc[2 * j + 1] = w * f2.y;
        }
    }

    int e0 = g_off[v], e1 = g_off[v + 1];
    int e = e0;
    for (; e + 4 <= e1; e += 4) {
        int s0 = g_csr_src[e],     s1 = g_csr_src[e + 1];
        int s2 = g_csr_src[e + 2], s3 = g_csr_src[e + 3];
        float n0 = g_csr_norm[e],     n1 = g_csr_norm[e + 1];
        float n2 = g_csr_norm[e + 2], n3 = g_csr_norm[e + 3];
        if (F == 256) {
            uint4 q0 = ((const uint4*)g_h16)[(size_t)s0 * 32 + lane];
            uint4 q1 = ((const uint4*)g_h16)[(size_t)s1 * 32 + lane];
            uint4 q2 = ((const uint4*)g_h16)[(size_t)s2 * 32 + lane];
            uint4 q3 = ((const uint4*)g_h16)[(size_t)s3 * 32 + lane];
            __half2 *h0 = (__half2*)&q0, *h1 = (__half2*)&q1;
            __half2 *h2 = (__half2*)&q2, *h3 = (__half2*)&q3;
#pragma unroll
            for (int j = 0; j < 4; j++) {
                float2 f0 = __half22float2(h0[j]), f1 = __half22float2(h1[j]);
                float2 f2 = __half22float2(h2[j]), f3 = __half22float2(h3[j]);
                acc[2 * j]     += n0 * f0.x + n1 * f1.x + n2 * f2.x + n3 * f3.x;
                acc[2 * j + 1] += n0 * f0.y + n1 * f1.y + n2 * f2.y + n3 * f3.y;
            }
        } else {
            uint2 q0 = ((const uint2*)g_h16)[(size_t)s0 * 32 + lane];
            uint2 q1 = ((const uint2*)g_h16)[(size_t)s1 * 32 + lane];
            uint2 q2 = ((const uint2*)g_h16)[(size_t)s2 * 32 + lane];
            uint2 q3 = ((const uint2*)g_h16)[(size_t)s3 * 32 + lane];
            __half2 *h0 = (__half2*)&q0, *h1 = (__half2*)&q1;
            __half2 *h2 = (__half2*)&q2, *h3 = (__half2*)&q3;
#pragma unroll
            for (int j = 0; j < 2; j++) {
                float2 f0 = __half22float2(h0[j]), f1 = __half22float2(h1[j]);
                float2 f2 = __half22float2(h2[j]), f3 = __half22float2(h3[j]);
                acc[2 * j]     += n0 * f0.x + n1 * f1.x + n2 * f2.x + n3 * f3.x;
                acc[2 * j + 1] += n0 * f0.y + n1 * f1.y + n2 * f2.y + n3 * f3.y;
            }
        }
    }
    for (; e < e1; e++) {
        int s = g_csr_src[e];
        float nrm = g_csr_norm[e];
        if (F == 256) {
            uint4 q0 = ((const uint4*)g_h16)[(size_t)s * 32 + lane];
            __half2* h0 = (__half2*)&q0;
#pragma unroll
            for (int j = 0; j < 4; j++) {
                float2 f2 = __half22float2(h0[j]);
                acc[2 * j] += nrm * f2.x; acc[2 * j + 1] += nrm * f2.y;
            }
        } else {
            uint2 q0 = ((const uint2*)g_h16)[(size_t)s * 32 + lane];
            __half2* h0 = (__half2*)&q0;
#pragma unroll
            for (int j = 0; j < 2; j++) {
                float2 f2 = __half22float2(h0[j]);
                acc[2 * j] += nrm * f2.x; acc[2 * j + 1] += nrm * f2.y;
            }
        }
    }

    if (F == 256) {
        uint4 hi = make_uint4(pack_hilo(acc[0], acc[1], 0), pack_hilo(acc[2], acc[3], 0),
                              pack_hilo(acc[4], acc[5], 0), pack_hilo(acc[6], acc[7], 0));
        uint4 lo = make_uint4(pack_hilo(acc[0], acc[1], 1), pack_hilo(acc[2], acc[3], 1),
                              pack_hilo(acc[4], acc[5], 1), pack_hilo(acc[6], acc[7], 1));
        ((uint4*)g_Ahi)[(size_t)v * 32 + lane] = hi;
        ((uint4*)g_Alo)[(size_t)v * 32 + lane] = lo;
    } else {
        uint2 hi = make_uint2(pack_hilo(acc[0], acc[1], 0), pack_hilo(acc[2], acc[3], 0));
        uint2 lo = make_uint2(pack_hilo(acc[0], acc[1], 1), pack_hilo(acc[2], acc[3], 1));
        ((uint2*)g_Ahi)[(size_t)v * 32 + lane] = hi;
        ((uint2*)g_Alo)[(size_t)v * 32 + lane] = lo;
    }
}

// ---------------- mma.sync bf16x3 GEMM, cp.async double-buffered ----------------
// BM=128, BN=128, BK=32; 8 warps (4x2), warp tile 32x64; output fp16 -> g_h16

#define SA 40
#define SB 136
#define A_ST (128 * SA)
#define B_ST (32 * SB)
#define GT_SMEM ((2 * 2 * A_ST + 2 * 2 * B_ST) * 2)

__global__ __launch_bounds__(256) void gemm_mma(const float* __restrict__ bias,
                                                int relu, int K, int wl) {
    extern __shared__ unsigned short smem[];
    unsigned short* Ah = smem;
    unsigned short* Al = Ah + 2 * A_ST;
    unsigned short* Bh = Al + 2 * A_ST;
    unsigned short* Bl = Bh + 2 * B_ST;
    __shared__ float bs[128];

    const unsigned short* GWh = g_Wh[wl];
    const unsigned short* GWl = g_Wl[wl];

    int tid = threadIdx.x, lane = tid & 31, wid = tid >> 5;
    int tm = blockIdx.x, tn = blockIdx.y;
    int wm = wid & 3, wn = wid >> 2;
    if (tid < 128) bs[tid] = bias[tn * 128 + tid];

    float c[16][4];
#pragma unroll
    for (int i = 0; i < 16; i++)
#pragma unroll
        for (int j = 0; j < 4; j++) c[i][j] = 0.f;

    u32 sAh = smem_u32(Ah), sAl = smem_u32(Al);
    u32 sBh = smem_u32(Bh), sBl = smem_u32(Bl);

    auto issue = [&](int st, int k0) {
#pragma unroll
        for (int i = 0; i < 2; i++) {
            int idx = tid + i * 256;
            int row = idx >> 2, cg = idx & 3;
            int grow = tm * 128 + row;
            u32 sz = (grow < NN) ? 16u : 0u;
            size_t gof = (size_t)grow * K + k0 + cg * 8;
            u32 dof = (u32)((st * A_ST + row * SA + cg * 8) * 2);
            cp16(sAh + dof, g_Ahi + gof, sz);
            cp16(sAl + dof, g_Alo + gof, sz);
        }
#pragma unroll
        for (int i = 0; i < 2; i++) {
            int idx = tid + i * 256;
            int row = idx >> 4, cg = idx & 15;
            size_t gof = (size_t)(k0 + row) * 256 + tn * 128 + cg * 8;
            u32 dof = (u32)((st * B_ST + row * SB + cg * 8) * 2);
            cp16(sBh + dof, GWh + gof, 16u);
            cp16(sBl + dof, GWl + gof, 16u);
        }
        cp_commit();
    };

    const int niter = K >> 5;
    issue(0, 0);
    for (int it = 0; it < niter; it++) {
        int cur = it & 1;
        if (it + 1 < niter) {
            issue((it + 1) & 1, (it + 1) << 5);
            cp_wait<1>();
        } else {
            cp_wait<0>();
        }
        __syncthreads();

        u32 aof = (u32)(cur * A_ST * 2), bof = (u32)(cur * B_ST * 2);
#pragma unroll
        for (int ks = 0; ks < 2; ks++) {
            u32 ah[2][4], al[2][4], bh[4][4], bl[4][4];
            int ar = wm * 32 + (lane & 15);
            int ac = ks * 16 + (lane >> 4) * 8;
            ldmx4(ah[0], sAh + aof + (u32)((ar * SA + ac) * 2));
            ldmx4(ah[1], sAh + aof + (u32)(((ar + 16) * SA + ac) * 2));
            ldmx4(al[0], sAl + aof + (u32)((ar * SA + ac) * 2));
            ldmx4(al[1], sAl + aof + (u32)(((ar + 16) * SA + ac) * 2));
            int br = ks * 16 + (lane & 15);
#pragma unroll
            for (int g = 0; g < 4; g++) {
                int bc = wn * 64 + g * 16 + (lane >> 4) * 8;
                ldmx4t(bh[g], sBh + bof + (u32)((br * SB + bc) * 2));
                ldmx4t(bl[g], sBl + bof + (u32)((br * SB + bc) * 2));
            }
#pragma unroll
            for (int mt = 0; mt < 2; mt++)
#pragma unroll
                for (int nt = 0; nt < 8; nt++) {
                    float* cc = c[mt * 8 + nt];
                    const u32* pbh = &bh[nt >> 1][(nt & 1) * 2];
                    const u32* pbl = &bl[nt >> 1][(nt & 1) * 2];
                    mma16816(cc, ah[mt], pbh);
                    mma16816(cc, ah[mt], pbl);
                    mma16816(cc, al[mt], pbh);
                }
        }
        __syncthreads();
    }

    // epilogue: bias + optional relu -> fp16 g_h16 [NN][256]
#pragma unroll
    for (int mt = 0; mt < 2; mt++) {
#pragma unroll
        for (int nt = 0; nt < 8; nt++) {
            int r0 = tm * 128 + wm * 32 + mt * 16 + (lane >> 2);
            int cl = wn * 64 + nt * 8 + (lane & 3) * 2;
            int col = tn * 128 + cl;
            float b0 = bs[cl], b1 = bs[cl + 1];
            float v0 = c[mt * 8 + nt][0] + b0;
            float v1 = c[mt * 8 + nt][1] + b1;
            float v2 = c[mt * 8 + nt][2] + b0;
            float v3 = c[mt * 8 + nt][3] + b1;
            if (relu) {
                v0 = fmaxf(v0, 0.f); v1 = fmaxf(v1, 0.f);
                v2 = fmaxf(v2, 0.f); v3 = fmaxf(v3, 0.f);
            }
            if (r0 < NN)
                *(__half2*)(g_h16 + (size_t)r0 * 256 + col) = __floats2half2_rn(v0, v1);
            if (r0 + 8 < NN)
                *(__half2*)(g_h16 + (size_t)(r0 + 8) * 256 + col) = __floats2half2_rn(v2, v3);
        }
    }
}

// ---------------- global max pool ----------------------------------------------

__device__ __forceinline__ void atomicMaxF(float* a, float v) {
    if (v >= 0.f) atomicMax((int*)a, __float_as_int(v));
    else          atomicMin((unsigned int*)a, __float_as_uint(v));
}

__global__ __launch_bounds__(256) void pool_kernel(const int* __restrict__ batch) {
    const __half* H = g_h16;
    int f = threadIdx.x;
    int v0 = blockIdx.x * 64;
    int vend = min(v0 + 64, NN);
    if (v0 >= NN) return;
    float m = -INFINITY;
    int cg = batch[v0];
    for (int v = v0; v < vend; v++) {
        int g = batch[v];
        if (g != cg) {
            atomicMaxF(&g_pool[cg * 256 + f], m);
            m = -INFINITY;
            cg = g;
        }
        m = fmaxf(m, __half2float(H[(size_t)v * 256 + f]));
    }
    atomicMaxF(&g_pool[cg * 256 + f], m);
}

// ---------------- dense head ----------------------------------------------------

__global__ __launch_bounds__(128) void head_kernel(const float* __restrict__ Wl2,
                                                   const float* __restrict__ bl2,
                                                   const float* __restrict__ Wl3,
                                                   const float* __restrict__ bl3,
                                                   const float* __restrict__ Wl,
                                                   const float* __restrict__ bl,
                                                   float* __restrict__ out) {
    __shared__ float gs[256];
    __shared__ float h2[128];
    __shared__ float h3[128];
    int g = blockIdx.x;
    int t = threadIdx.x;
    gs[t]       = g_pool[g * 256 + t];
    gs[t + 128] = g_pool[g * 256 + 128 + t];
    __syncthreads();
    float a = bl2[t];
    for (int k = 0; k < 256; k++) a += gs[k] * Wl2[k * 128 + t];
    h2[t] = fmaxf(a, 0.f);
    __syncthreads();
    float b = bl3[t];
    for (int k = 0; k < 128; k++) b += h2[k] * Wl3[k * 128 + t];
    h3[t] = fmaxf(b, 0.f);
    __syncthreads();
    if (t < 10) {
        float c = bl[t];
        for (int k = 0; k < 128; k++) c += h3[k] * Wl[k * 10 + t];
        out[g * 10 + t] = c;
    }
}

// ---------------- launch ---------------------------------------------------------

extern "C" void kernel_launch(void* const* d_in, const int* in_sizes, int n_in,
                              void* d_out, int out_size) {
    const float* x     = (const float*)d_in[0];
    const int*   ei    = (const int*)d_in[1];
    const int*   batch = (const int*)d_in[2];
    const float *W1 = (const float*)d_in[3],  *b1 = (const float*)d_in[4];
    const float *W2 = (const float*)d_in[5],  *b2 = (const float*)d_in[6];
    const float *W3 = (const float*)d_in[7],  *b3 = (const float*)d_in[8];
    const float *W4 = (const float*)d_in[9],  *b4 = (const float*)d_in[10];
    const float *Wl2 = (const float*)d_in[11], *bl2 = (const float*)d_in[12];
    const float *Wl3 = (const float*)d_in[13], *bl3 = (const float*)d_in[14];
    const float *Wl  = (const float*)d_in[15], *bl  = (const float*)d_in[16];
    float* out = (float*)d_out;

    const int* esrc = ei;
    const int* edst = ei + NE;

    cudaFuncSetAttribute(gemm_mma, cudaFuncAttributeMaxDynamicSharedMemorySize, GT_SMEM);

    // preprocessing + weight conversion
    zero_cnt_kernel<<<(NN + 255) / 256, 256>>>();
    count_kernel<<<(NE + 255) / 256, 256>>>(edst);
    conv_w_all<<<(163840 + 255) / 256, 256>>>(W2, W3, W4);
    scan1_kernel<<<SCAN_B, 256>>>();
    scan2_kernel<<<1, 256>>>();
    finalize_kernel<<<(NN + 255) / 256, 256>>>();
    fill_kernel<<<(NE + 255) / 256, 256>>>(esrc, edst);

    const int AGG_GRID = (NN + 7) / 8;
    dim3 ggrid(TM, 2);

    // layer 1: fused agg9 + GEMM(9->128) + relu -> g_h16 (stride 128)
    layer1_kernel<<<AGG_GRID, 256>>>(x, W1, b1);

    // layer 2: agg(F=128) -> hi/lo ; mma GEMM K=128 -> g_h16 (stride 256)
    agg_hilo<128><<<AGG_GRID, 256>>>();
    gemm_mma<<<ggrid, 256, GT_SMEM>>>(b2, 1, 128, 0);

    // layer 3
    agg_hilo<256><<<AGG_GRID, 256>>>();
    gemm_mma<<<ggrid, 256, GT_SMEM>>>(b3, 1, 256, 1);

    // layer 4 (no relu)
    agg_hilo<256><<<AGG_GRID, 256>>>();
    gemm_mma<<<ggrid, 256, GT_SMEM>>>(b4, 0, 256, 2);

    // pool + head
    pool_kernel<<<(NN + 63) / 64, 256>>>(batch);
    head_kernel<<<NG, 128>>>(Wl2, bl2, Wl3, bl3, Wl, bl, out);
}

// round 10
// speedup vs baseline: 2.5672x; 1.1979x over previous
#include <cuda_runtime.h>
#include <cuda_bf16.h>
#include <cuda_fp16.h>
#include <math.h>

#define NN 50000
#define NE 800000
#define NG 64
#define SCAN_B ((NN + 255) / 256)
#define TM ((NN + 127) / 128)   // 391 m-tiles

typedef unsigned long long u64;
typedef unsigned int u32;

// ---------------- scratch (device globals; no allocation allowed) -------------
__device__ __half g_h16[(size_t)NN * 256];   // layer activations, fp16
__device__ __half g_A16[(size_t)NN * 256];   // aggregated activations (GEMM A), fp16
__device__ float g_dinv[NN];
__device__ int   g_cnt[NN];
__device__ int   g_off[NN + 1];
__device__ int   g_cur[NN];
__device__ int   g_bsum[SCAN_B];
__device__ int   g_csr_src[NE];
__device__ float g_csr_norm[NE];
__device__ float g_pool[NG * 256];
// fp16 hi/lo weights per layer (0:W2 K=128, 1:W3, 2:W4)
__device__ unsigned short g_Wh[3][256 * 256];
__device__ unsigned short g_Wl[3][256 * 256];

// ---------------- PTX helpers ---------------------------------------------------

__device__ __forceinline__ u32 smem_u32(const void* p) {
    u32 a;
    asm("{ .reg .u64 t; cvta.to.shared.u64 t, %1; cvt.u32.u64 %0, t; }" : "=r"(a) : "l"(p));
    return a;
}
__device__ __forceinline__ void ldmx4(u32* r, u32 a) {
    asm volatile("ldmatrix.sync.aligned.m8n8.x4.shared.b16 {%0,%1,%2,%3}, [%4];"
                 : "=r"(r[0]), "=r"(r[1]), "=r"(r[2]), "=r"(r[3]) : "r"(a));
}
__device__ __forceinline__ void ldmx4t(u32* r, u32 a) {
    asm volatile("ldmatrix.sync.aligned.m8n8.x4.trans.shared.b16 {%0,%1,%2,%3}, [%4];"
                 : "=r"(r[0]), "=r"(r[1]), "=r"(r[2]), "=r"(r[3]) : "r"(a));
}
__device__ __forceinline__ void mma16816h(float* c, const u32* a, const u32* b) {
    asm volatile(
        "mma.sync.aligned.m16n8k16.row.col.f32.f16.f16.f32 "
        "{%0,%1,%2,%3}, {%4,%5,%6,%7}, {%8,%9}, {%0,%1,%2,%3};"
        : "+f"(c[0]), "+f"(c[1]), "+f"(c[2]), "+f"(c[3])
        : "r"(a[0]), "r"(a[1]), "r"(a[2]), "r"(a[3]), "r"(b[0]), "r"(b[1]));
}
__device__ __forceinline__ void cp16(u32 dst, const void* src, u32 sz) {
    asm volatile("cp.async.cg.shared.global [%0], [%1], 16, %2;"
                 :: "r"(dst), "l"(src), "r"(sz) : "memory");
}
__device__ __forceinline__ void cp_commit() {
    asm volatile("cp.async.commit_group;" ::: "memory");
}
template <int N>
__device__ __forceinline__ void cp_wait() {
    asm volatile("cp.async.wait_group %0;" :: "n"(N) : "memory");
}

// ---------------- preprocessing ----------------------------------------------

__global__ void zero_cnt_kernel() {
    int i = blockIdx.x * blockDim.x + threadIdx.x;
    if (i < NN) g_cnt[i] = 0;
}

__global__ void count_kernel(const int* __restrict__ dst) {
    int e = blockIdx.x * blockDim.x + threadIdx.x;
    if (e < NE) atomicAdd(&g_cnt[dst[e]], 1);
}

__global__ void scan1_kernel() {
    __shared__ int s[256];
    int tid = threadIdx.x;
    int idx = blockIdx.x * 256 + tid;
    int v = (idx < NN) ? g_cnt[idx] : 0;
    s[tid] = v;
    __syncthreads();
#pragma unroll
    for (int o = 1; o < 256; o <<= 1) {
        int t = (tid >= o) ? s[tid - o] : 0;
        __syncthreads();
        s[tid] += t;
        __syncthreads();
    }
    if (idx < NN) g_off[idx] = s[tid] - v;
    if (tid == 255) g_bsum[blockIdx.x] = s[255];
}

__global__ void scan2_kernel() {
    __shared__ int s[256];
    int tid = threadIdx.x;
    int v = (tid < SCAN_B) ? g_bsum[tid] : 0;
    s[tid] = v;
    __syncthreads();
#pragma unroll
    for (int o = 1; o < 256; o <<= 1) {
        int t = (tid >= o) ? s[tid - o] : 0;
        __syncthreads();
        s[tid] += t;
        __syncthreads();
    }
    if (tid < SCAN_B) g_bsum[tid] = s[tid] - v;
}

__global__ void finalize_kernel() {
    int v = blockIdx.x * blockDim.x + threadIdx.x;
    if (v < NN) {
        int off = g_off[v] + g_bsum[v >> 8];
        g_off[v] = off;
        g_cur[v] = off;
        g_dinv[v] = rsqrtf((float)g_cnt[v] + 1.0f);
    }
    if (v < NG * 256) g_pool[v] = -INFINITY;   // fused pool init
    if (v == 0) g_off[NN] = NE;
}

__global__ void fill_kernel(const int* __restrict__ src,
                            const int* __restrict__ dst) {
    int e = blockIdx.x * blockDim.x + threadIdx.x;
    if (e < NE) {
        int s = src[e];
        int d = dst[e];
        int pos = atomicAdd(&g_cur[d], 1);
        g_csr_src[pos] = s;
        g_csr_norm[pos] = g_dinv[s] * g_dinv[d];
    }
}

// ---------------- weight conversion: fp16 hi/lo, all layers ---------------------

__global__ void conv_w_all(const float* __restrict__ W2,
                           const float* __restrict__ W3,
                           const float* __restrict__ W4) {
    int i = blockIdx.x * 256 + threadIdx.x;
    const float* W;
    unsigned short *dh, *dl;
    int off;
    if (i < 32768)       { W = W2; off = i;           dh = g_Wh[0]; dl = g_Wl[0]; }
    else if (i < 98304)  { W = W3; off = i - 32768;   dh = g_Wh[1]; dl = g_Wl[1]; }
    else if (i < 163840) { W = W4; off = i - 98304;   dh = g_Wh[2]; dl = g_Wl[2]; }
    else return;
    float v = W[off];
    __half h = __float2half_rn(v);
    __half l = __float2half_rn(v - __half2float(h));
    dh[off] = __half_as_ushort(h);
    dl[off] = __half_as_ushort(l);
}

// ---------------- fused layer 1: agg9 + [N,9]@[9,128] + bias + relu -> fp16 -----

__global__ __launch_bounds__(256) void layer1_kernel(const float* __restrict__ x,
                                                     const float* __restrict__ W1,
                                                     const float* __restrict__ b1) {
    __shared__ float Ws[9 * 128];
    __shared__ float Bs[128];
    int tid = threadIdx.x;
    for (int i = tid; i < 9 * 128; i += 256) Ws[i] = W1[i];
    if (tid < 128) Bs[tid] = b1[tid];
    __syncthreads();

    int warp = (blockIdx.x * 256 + tid) >> 5;
    int lane = tid & 31;
    if (warp >= NN) return;
    int v = warp;
    float dv = g_dinv[v];
    float acc = 0.f;
    if (lane < 9) acc = dv * dv * x[v * 9 + lane];
    int e0 = g_off[v], e1 = g_off[v + 1];
    for (int e = e0; e < e1; e++) {
        int s = g_csr_src[e];
        float nrm = g_csr_norm[e];
        if (lane < 9) acc += nrm * x[s * 9 + lane];
    }
    float ak[9];
#pragma unroll
    for (int k = 0; k < 9; k++) ak[k] = __shfl_sync(0xffffffffu, acc, k);

    int f = lane * 4;
    float o0 = Bs[f], o1 = Bs[f + 1], o2 = Bs[f + 2], o3 = Bs[f + 3];
#pragma unroll
    for (int k = 0; k < 9; k++) {
        float a = ak[k];
        const float* wr = &Ws[k * 128 + f];
        o0 += a * wr[0]; o1 += a * wr[1]; o2 += a * wr[2]; o3 += a * wr[3];
    }
    o0 = fmaxf(o0, 0.f); o1 = fmaxf(o1, 0.f);
    o2 = fmaxf(o2, 0.f); o3 = fmaxf(o3, 0.f);
    __half2* dst = (__half2*)(g_h16 + (size_t)v * 128 + f);
    dst[0] = __floats2half2_rn(o0, o1);
    dst[1] = __floats2half2_rn(o2, o3);
}

// ---------------- aggregation: gather fp16 rows -> fp16 A operand ---------------

template <int F>
__global__ __launch_bounds__(256) void agg_f16() {
    int warp = (blockIdx.x * blockDim.x + threadIdx.x) >> 5;
    int lane = threadIdx.x & 31;
    if (warp >= NN) return;
    const int v = warp;

    float acc[F / 32];
    float dv = g_dinv[v];
    float w = dv * dv;
    if (F == 256) {
        uint4 q = ((const uint4*)g_h16)[(size_t)v * 32 + lane];
        __half2* h = (__half2*)&q;
#pragma unroll
        for (int j = 0; j < 4; j++) {
            float2 f2 = __half22float2(h[j]);
            acc[2 * j] = w * f2.x; acc[2 * j + 1] = w * f2.y;
        }
    } else {
        uint2 q = ((const uint2*)g_h16)[(size_t)v * 32 + lane];
        __half2* h = (__half2*)&q;
#pragma unroll
        for (int j = 0; j < 2; j++) {
            float2 f2 = __half22float2(h[j]);
            acc[2 * j] = w * f2.x; acc[2 * j + 1] = w * f2.y;
        }
    }

    int e0 = g_off[v], e1 = g_off[v + 1];
    int e = e0;
    for (; e + 4 <= e1; e += 4) {
        int s0 = g_csr_src[e],     s1 = g_csr_src[e + 1];
        int s2 = g_csr_src[e + 2], s3 = g_csr_src[e + 3];
        float n0 = g_csr_norm[e],     n1 = g_csr_norm[e + 1];
        float n2 = g_csr_norm[e + 2], n3 = g_csr_norm[e + 3];
        if (F == 256) {
            uint4 q0 = ((const uint4*)g_h16)[(size_t)s0 * 32 + lane];
            uint4 q1 = ((const uint4*)g_h16)[(size_t)s1 * 32 + lane];
            uint4 q2 = ((const uint4*)g_h16)[(size_t)s2 * 32 + lane];
            uint4 q3 = ((const uint4*)g_h16)[(size_t)s3 * 32 + lane];
            __half2 *h0 = (__half2*)&q0, *h1 = (__half2*)&q1;
            __half2 *h2 = (__half2*)&q2, *h3 = (__half2*)&q3;
#pragma unroll
            for (int j = 0; j < 4; j++) {
                float2 f0 = __half22float2(h0[j]), f1 = __half22float2(h1[j]);
                float2 f2 = __half22float2(h2[j]), f3 = __half22float2(h3[j]);
                acc[2 * j]     += n0 * f0.x + n1 * f1.x + n2 * f2.x + n3 * f3.x;
                acc[2 * j + 1] += n0 * f0.y + n1 * f1.y + n2 * f2.y + n3 * f3.y;
            }
        } else {
            uint2 q0 = ((const uint2*)g_h16)[(size_t)s0 * 32 + lane];
            uint2 q1 = ((const uint2*)g_h16)[(size_t)s1 * 32 + lane];
            uint2 q2 = ((const uint2*)g_h16)[(size_t)s2 * 32 + lane];
            uint2 q3 = ((const uint2*)g_h16)[(size_t)s3 * 32 + lane];
            __half2 *h0 = (__half2*)&q0, *h1 = (__half2*)&q1;
            __half2 *h2 = (__half2*)&q2, *h3 = (__half2*)&q3;
#pragma unroll
            for (int j = 0; j < 2; j++) {
                float2 f0 = __half22float2(h0[j]), f1 = __half22float2(h1[j]);
                float2 f2 = __half22float2(h2[j]), f3 = __half22float2(h3[j]);
                acc[2 * j]     += n0 * f0.x + n1 * f1.x + n2 * f2.x + n3 * f3.x;
                acc[2 * j + 1] += n0 * f0.y + n1 * f1.y + n2 * f2.y + n3 * f3.y;
            }
        }
    }
    for (; e < e1; e++) {
        int s = g_csr_src[e];
        float nrm = g_csr_norm[e];
        if (F == 256) {
            uint4 q0 = ((const uint4*)g_h16)[(size_t)s * 32 + lane];
            __half2* h0 = (__half2*)&q0;
#pragma unroll
            for (int j = 0; j < 4; j++) {
                float2 f2 = __half22float2(h0[j]);
                acc[2 * j] += nrm * f2.x; acc[2 * j + 1] += nrm * f2.y;
            }
        } else {
            uint2 q0 = ((const uint2*)g_h16)[(size_t)s * 32 + lane];
            __half2* h0 = (__half2*)&q0;
#pragma unroll
            for (int j = 0; j < 2; j++) {
                float2 f2 = __half22float2(h0[j]);
                acc[2 * j] += nrm * f2.x; acc[2 * j + 1] += nrm * f2.y;
            }
        }
    }

    if (F == 256) {
        uint4 o;
        __half2* ho = (__half2*)&o;
#pragma unroll
        for (int j = 0; j < 4; j++) ho[j] = __floats2half2_rn(acc[2 * j], acc[2 * j + 1]);
        ((uint4*)g_A16)[(size_t)v * 32 + lane] = o;
    } else {
        uint2 o;
        __half2* ho = (__half2*)&o;
#pragma unroll
        for (int j = 0; j < 2; j++) ho[j] = __floats2half2_rn(acc[2 * j], acc[2 * j + 1]);
        ((uint2*)g_A16)[(size_t)v * 32 + lane] = o;
    }
}

// ---------------- mma.sync fp16x2 GEMM, cp.async double-buffered ----------------
// BM=128, BN=128, BK=32; 8 warps (4x2), warp tile 32x64; output fp16 -> g_h16

#define SA 40
#define SB 136
#define A_ST (128 * SA)
#define B_ST (32 * SB)
#define GT_SMEM ((2 * A_ST + 2 * 2 * B_ST) * 2)

__global__ __launch_bounds__(256) void gemm_mma(const float* __restrict__ bias,
                                                int relu, int K, int wl) {
    extern __shared__ unsigned short smem[];
    unsigned short* Aa = smem;                  // [2][A_ST]
    unsigned short* Bh = Aa + 2 * A_ST;         // [2][B_ST]
    unsigned short* Bl = Bh + 2 * B_ST;
    __shared__ float bs[128];

    const unsigned short* GWh = g_Wh[wl];
    const unsigned short* GWl = g_Wl[wl];

    int tid = threadIdx.x, lane = tid & 31, wid = tid >> 5;
    int tm = blockIdx.x, tn = blockIdx.y;
    int wm = wid & 3, wn = wid >> 2;
    if (tid < 128) bs[tid] = bias[tn * 128 + tid];

    float c[16][4];
#pragma unroll
    for (int i = 0; i < 16; i++)
#pragma unroll
        for (int j = 0; j < 4; j++) c[i][j] = 0.f;

    u32 sAa = smem_u32(Aa);
    u32 sBh = smem_u32(Bh), sBl = smem_u32(Bl);

    auto issue = [&](int st, int k0) {
#pragma unroll
        for (int i = 0; i < 2; i++) {
            int idx = tid + i * 256;
            int row = idx >> 2, cg = idx & 3;
            int grow = tm * 128 + row;
            u32 sz = (grow < NN) ? 16u : 0u;
            size_t gof = (size_t)grow * K + k0 + cg * 8;
            u32 dof = (u32)((st * A_ST + row * SA + cg * 8) * 2);
            cp16(sAa + dof, g_A16 + gof, sz);
        }
#pragma unroll
        for (int i = 0; i < 2; i++) {
            int idx = tid + i * 256;
            int row = idx >> 4, cg = idx & 15;
            size_t gof = (size_t)(k0 + row) * 256 + tn * 128 + cg * 8;
            u32 dof = (u32)((st * B_ST + row * SB + cg * 8) * 2);
            cp16(sBh + dof, GWh + gof, 16u);
            cp16(sBl + dof, GWl + gof, 16u);
        }
        cp_commit();
    };

    const int niter = K >> 5;
    issue(0, 0);
    for (int it = 0; it < niter; it++) {
        int cur = it & 1;
        if (it + 1 < niter) {
            issue((it + 1) & 1, (it + 1) << 5);
            cp_wait<1>();
        } else {
            cp_wait<0>();
        }
        __syncthreads();

        u32 aof = (u32)(cur * A_ST * 2), bof = (u32)(cur * B_ST * 2);
#pragma unroll
        for (int ks = 0; ks < 2; ks++) {
            u32 ah[2][4], bh[4][4], bl[4][4];
            int ar = wm * 32 + (lane & 15);
            int ac = ks * 16 + (lane >> 4) * 8;
            ldmx4(ah[0], sAa + aof + (u32)((ar * SA + ac) * 2));
            ldmx4(ah[1], sAa + aof + (u32)(((ar + 16) * SA + ac) * 2));
            int br = ks * 16 + (lane & 15);
#pragma unroll
            for (int g = 0; g < 4; g++) {
                int bc = wn * 64 + g * 16 + (lane >> 4) * 8;
                ldmx4t(bh[g], sBh + bof + (u32)((br * SB + bc) * 2));
                ldmx4t(bl[g], sBl + bof + (u32)((br * SB + bc) * 2));
            }
#pragma unroll
            for (int mt = 0; mt < 2; mt++)
#pragma unroll
                for (int nt = 0; nt < 8; nt++) {
                    float* cc = c[mt * 8 + nt];
                    const u32* pbh = &bh[nt >> 1][(nt & 1) * 2];
                    const u32* pbl = &bl[nt >> 1][(nt & 1) * 2];
                    mma16816h(cc, ah[mt], pbh);
                    mma16816h(cc, ah[mt], pbl);
                }
        }
        __syncthreads();
    }

    // epilogue: bias + optional relu -> fp16 g_h16 [NN][256]
#pragma unroll
    for (int mt = 0; mt < 2; mt++) {
#pragma unroll
        for (int nt = 0; nt < 8; nt++) {
            int r0 = tm * 128 + wm * 32 + mt * 16 + (lane >> 2);
            int cl = wn * 64 + nt * 8 + (lane & 3) * 2;
            int col = tn * 128 + cl;
            float b0 = bs[cl], b1 = bs[cl + 1];
            float v0 = c[mt * 8 + nt][0] + b0;
            float v1 = c[mt * 8 + nt][1] + b1;
            float v2 = c[mt * 8 + nt][2] + b0;
            float v3 = c[mt * 8 + nt][3] + b1;
            if (relu) {
                v0 = fmaxf(v0, 0.f); v1 = fmaxf(v1, 0.f);
                v2 = fmaxf(v2, 0.f); v3 = fmaxf(v3, 0.f);
            }
            if (r0 < NN)
                *(__half2*)(g_h16 + (size_t)r0 * 256 + col) = __floats2half2_rn(v0, v1);
            if (r0 + 8 < NN)
                *(__half2*)(g_h16 + (size_t)(r0 + 8) * 256 + col) = __floats2half2_rn(v2, v3);
        }
    }
}

// ---------------- global max pool ----------------------------------------------

__device__ __forceinline__ void atomicMaxF(float* a, float v) {
    if (v >= 0.f) atomicMax((int*)a, __float_as_int(v));
    else          atomicMin((unsigned int*)a, __float_as_uint(v));
}

__global__ __launch_bounds__(256) void pool_kernel(const int* __restrict__ batch) {
    const __half* H = g_h16;
    int f = threadIdx.x;
    int v0 = blockIdx.x * 64;
    int vend = min(v0 + 64, NN);
    if (v0 >= NN) return;
    float m = -INFINITY;
    int cg = batch[v0];
    for (int v = v0; v < vend; v++) {
        int g = batch[v];
        if (g != cg) {
            atomicMaxF(&g_pool[cg * 256 + f], m);
            m = -INFINITY;
            cg = g;
        }
        m = fmaxf(m, __half2float(H[(size_t)v * 256 + f]));
    }
    atomicMaxF(&g_pool[cg * 256 + f], m);
}

// ---------------- dense head ----------------------------------------------------

__global__ __launch_bounds__(128) void head_kernel(const float* __restrict__ Wl2,
                                                   const float* __restrict__ bl2,
                                                   const float* __restrict__ Wl3,
                                                   const float* __restrict__ bl3,
                                                   const float* __restrict__ Wl,
                                                   const float* __restrict__ bl,
                                                   float* __restrict__ out) {
    __shared__ float gs[256];
    __shared__ float h2[128];
    __shared__ float h3[128];
    int g = blockIdx.x;
    int t = threadIdx.x;
    gs[t]       = g_pool[g * 256 + t];
    gs[t + 128] = g_pool[g * 256 + 128 + t];
    __syncthreads();
    float a = bl2[t];
    for (int k = 0; k < 256; k++) a += gs[k] * Wl2[k * 128 + t];
    h2[t] = fmaxf(a, 0.f);
    __syncthreads();
    float b = bl3[t];
    for (int k = 0; k < 128; k++) b += h2[k] * Wl3[k * 128 + t];
    h3[t] = fmaxf(b, 0.f);
    __syncthreads();
    if (t < 10) {
        float c = bl[t];
        for (int k = 0; k < 128; k++) c += h3[k] * Wl[k * 10 + t];
        out[g * 10 + t] = c;
    }
}

// ---------------- launch ---------------------------------------------------------

extern "C" void kernel_launch(void* const* d_in, const int* in_sizes, int n_in,
                              void* d_out, int out_size) {
    const float* x     = (const float*)d_in[0];
    const int*   ei    = (const int*)d_in[1];
    const int*   batch = (const int*)d_in[2];
    const float *W1 = (const float*)d_in[3],  *b1 = (const float*)d_in[4];
    const float *W2 = (const float*)d_in[5],  *b2 = (const float*)d_in[6];
    const float *W3 = (const float*)d_in[7],  *b3 = (const float*)d_in[8];
    const float *W4 = (const float*)d_in[9],  *b4 = (const float*)d_in[10];
    const float *Wl2 = (const float*)d_in[11], *bl2 = (const float*)d_in[12];
    const float *Wl3 = (const float*)d_in[13], *bl3 = (const float*)d_in[14];
    const float *Wl  = (const float*)d_in[15], *bl  = (const float*)d_in[16];
    float* out = (float*)d_out;

    const int* esrc = ei;
    const int* edst = ei + NE;

    cudaFuncSetAttribute(gemm_mma, cudaFuncAttributeMaxDynamicSharedMemorySize, GT_SMEM);

    // preprocessing + weight conversion
    zero_cnt_kernel<<<(NN + 255) / 256, 256>>>();
    count_kernel<<<(NE + 255) / 256, 256>>>(edst);
    conv_w_all<<<(163840 + 255) / 256, 256>>>(W2, W3, W4);
    scan1_kernel<<<SCAN_B, 256>>>();
    scan2_kernel<<<1, 256>>>();
    finalize_kernel<<<(NN + 255) / 256, 256>>>();
    fill_kernel<<<(NE + 255) / 256, 256>>>(esrc, edst);

    const int AGG_GRID = (NN + 7) / 8;
    dim3 ggrid(TM, 2);

    // layer 1: fused agg9 + GEMM(9->128) + relu -> g_h16 (stride 128)
    layer1_kernel<<<AGG_GRID, 256>>>(x, W1, b1);

    // layer 2: agg(F=128) -> fp16 A ; mma GEMM K=128 -> g_h16 (stride 256)
    agg_f16<128><<<AGG_GRID, 256>>>();
    gemm_mma<<<ggrid, 256, GT_SMEM>>>(b2, 1, 128, 0);

    // layer 3
    agg_f16<256><<<AGG_GRID, 256>>>();
    gemm_mma<<<ggrid, 256, GT_SMEM>>>(b3, 1, 256, 1);

    // layer 4 (no relu)
    agg_f16<256><<<AGG_GRID, 256>>>();
    gemm_mma<<<ggrid, 256, GT_SMEM>>>(b4, 0, 256, 2);

    // pool + head
    pool_kernel<<<(NN + 63) / 64, 256>>>(batch);
    head_kernel<<<NG, 128>>>(Wl2, bl2, Wl3, bl3, Wl, bl, out);
}